// round 5
// baseline (speedup 1.0000x reference)
#include <cuda_runtime.h>
#include <math.h>

#define NPTS   1000
#define BATCH  2
#define BNODES 2000
#define KNN    8
#define NEDGE  (BNODES*KNN)
#define NPAIR  499500   // NPTS*(NPTS-1)/2

typedef unsigned long long ull;

// packed f32x2 helpers (Blackwell: fma.rn.f32x2 — PTX-only, ptxas won't emit it)
__device__ __forceinline__ ull pk2(float x) {
    ull r; asm("mov.b64 %0, {%1, %1};" : "=l"(r) : "f"(x)); return r;
}
__device__ __forceinline__ void fma2(ull& d, ull a, ull b) {
    asm("fma.rn.f32x2 %0, %1, %2, %0;" : "+l"(d) : "l"(a), "l"(b));
}
__device__ __forceinline__ void unpk(ull v, float& lo, float& hi) {
    asm("mov.b64 {%0, %1}, %2;" : "=f"(lo), "=f"(hi) : "l"(v));
}

// ---------------- scratch (static __device__; no allocations) ----------------
__device__ float g_sq[BNODES];
__device__ int   g_idx[NEDGE];
__device__ __align__(16) float g_U[BNODES*256];
__device__ __align__(16) float g_V[BNODES*256];
__device__ __align__(16) float g_G[BATCH*NPTS*NPTS];   // per-batch dot matrix
__device__ __align__(16) float g_cat[BNODES*672];
__device__ __align__(16) float g_smh[BNODES*256];
__device__ __align__(16) float g_sf[BNODES*128];
__device__ __align__(16) float g_hi[BNODES*128];
__device__ __align__(16) float g_hjg[BNODES*128];
__device__ __align__(16) float g_hg[BATCH*128];

// ================= merged prep kernel: xxt tiles + UV gemm tiles ==============
// blocks [0, 128):        X@X^T 128x128 tiles (8x8 grid x 2 batches), writes G + diag->g_sq
// blocks [128, 128+32*nuvn): dual GEMM U = x@(w1[:C]-w1[C:]), V = x@w1[C:]
__global__ void __launch_bounds__(256)
prep_kernel(const float* __restrict__ x, int lda, int C, int H,
            const float* __restrict__ w1,
            float* __restrict__ G, float* __restrict__ U, float* __restrict__ V) {
    __shared__ __align__(16) float sm[4224];
    int bid = blockIdx.x;
    int tid = threadIdx.x;

    if (bid < 128) {
        // ---------------- xxt tile ----------------
        // As: sm[0..2112), Bs: sm[2112..4224), both [16][132]
        float* As = sm;
        float* Bs = sm + 2112;
        int b  = bid >> 6;
        int r6 = bid & 63;
        int m0 = (r6 >> 3) * 128, n0 = (r6 & 7) * 128;
        const float* xb = x + (size_t)b * NPTS * lda;
        int lrow = tid >> 1, lk8 = (tid & 1) * 8;
        int tx = tid & 15, ty = tid >> 4;
        ull acc2[8][4];
        #pragma unroll
        for (int r = 0; r < 8; r++)
            #pragma unroll
            for (int q = 0; q < 4; q++) acc2[r][q] = 0ull;

        int ar = m0 + lrow, br = n0 + lrow;
        for (int k0 = 0; k0 < C; k0 += 16) {
            #pragma unroll
            for (int q = 0; q < 8; q++) {
                int k = k0 + lk8 + q;
                As[(lk8 + q) * 132 + lrow] = (ar < NPTS && k < C) ? xb[(size_t)ar * lda + k] : 0.f;
                Bs[(lk8 + q) * 132 + lrow] = (br < NPTS && k < C) ? xb[(size_t)br * lda + k] : 0.f;
            }
            __syncthreads();
            #pragma unroll
            for (int kk = 0; kk < 16; kk++) {
                float a[8];
                *(float4*)&a[0] = *(const float4*)&As[kk * 132 + ty * 8];
                *(float4*)&a[4] = *(const float4*)&As[kk * 132 + ty * 8 + 4];
                ull bp[4];
                {
                    ulonglong2 t0 = *(const ulonglong2*)&Bs[kk * 132 + tx * 8];
                    ulonglong2 t1 = *(const ulonglong2*)&Bs[kk * 132 + tx * 8 + 4];
                    bp[0] = t0.x; bp[1] = t0.y; bp[2] = t1.x; bp[3] = t1.y;
                }
                #pragma unroll
                for (int r = 0; r < 8; r++) {
                    ull ap = pk2(a[r]);
                    #pragma unroll
                    for (int q = 0; q < 4; q++) fma2(acc2[r][q], ap, bp[q]);
                }
            }
            __syncthreads();
        }
        #pragma unroll
        for (int r = 0; r < 8; r++) {
            int i = m0 + ty * 8 + r;
            if (i >= NPTS) continue;
            float av[8];
            #pragma unroll
            for (int q = 0; q < 4; q++) unpk(acc2[r][q], av[2 * q], av[2 * q + 1]);
            #pragma unroll
            for (int c = 0; c < 8; c++) {
                int j = n0 + tx * 8 + c;
                if (j < NPTS) {
                    G[((size_t)b * NPTS + i) * NPTS + j] = av[c];
                    if (i == j) g_sq[b * NPTS + i] = av[c];
                }
            }
        }
    } else {
        // ---------------- UV dual GEMM tile (64x64, 4x4) ----------------
        // As: sm[0..1088), B1s: sm[1088..2176), B2s: sm[2176..3264), all [16][68]
        float* As  = sm;
        float* B1s = sm + 1088;
        float* B2s = sm + 2176;
        int bid2 = bid - 128;
        int m0 = (bid2 & 31) * 64, n0 = (bid2 >> 5) * 64;
        const float* B1 = w1;
        const float* B2 = w1 + (size_t)C * H;
        int tx = tid & 15, ty = tid >> 4;
        ull aU[4][2], aV[4][2];
        #pragma unroll
        for (int r = 0; r < 4; r++) {
            aU[r][0] = aU[r][1] = 0ull;
            aV[r][0] = aV[r][1] = 0ull;
        }
        int la_m = tid >> 2;
        int la_k = (tid & 3) << 2;
        int lb_k = tid >> 4;
        int lb_n = (tid & 15) << 2;

        for (int k0 = 0; k0 < C; k0 += 16) {
            int am = m0 + la_m;
            #pragma unroll
            for (int q = 0; q < 4; q++) {
                int ak = k0 + la_k + q;
                As[(la_k + q) * 68 + la_m] = (am < BNODES && ak < C) ? x[(size_t)am * lda + ak] : 0.f;
            }
            int bk = k0 + lb_k;
            #pragma unroll
            for (int q = 0; q < 4; q++) {
                int bn = n0 + lb_n + q;
                float v1 = 0.f, v2 = 0.f;
                if (bk < C && bn < H) {
                    size_t o = (size_t)bk * H + bn;
                    v1 = B1[o]; v2 = B2[o];
                }
                B1s[lb_k * 68 + lb_n + q] = v1 - v2;
                B2s[lb_k * 68 + lb_n + q] = v2;
            }
            __syncthreads();
            #pragma unroll
            for (int kk = 0; kk < 16; kk++) {
                float4 af = *(const float4*)&As[kk * 68 + (ty << 2)];
                ulonglong2 b1t = *(const ulonglong2*)&B1s[kk * 68 + (tx << 2)];
                ulonglong2 b2t = *(const ulonglong2*)&B2s[kk * 68 + (tx << 2)];
                float a[4] = {af.x, af.y, af.z, af.w};
                #pragma unroll
                for (int r = 0; r < 4; r++) {
                    ull ap = pk2(a[r]);
                    fma2(aU[r][0], ap, b1t.x);
                    fma2(aU[r][1], ap, b1t.y);
                    fma2(aV[r][0], ap, b2t.x);
                    fma2(aV[r][1], ap, b2t.y);
                }
            }
            __syncthreads();
        }
        #pragma unroll
        for (int r = 0; r < 4; r++) {
            int m = m0 + (ty << 2) + r;
            if (m >= BNODES) continue;
            float u[4], v[4];
            unpk(aU[r][0], u[0], u[1]); unpk(aU[r][1], u[2], u[3]);
            unpk(aV[r][0], v[0], v[1]); unpk(aV[r][1], v[2], v[3]);
            #pragma unroll
            for (int c = 0; c < 4; c++) {
                int n = n0 + (tx << 2) + c;
                if (n >= H) continue;
                U[(size_t)m * H + n] = u[c];
                V[(size_t)m * H + n] = v[c];
            }
        }
    }
}

// ---------------- warp-parallel top-8 (ties -> lowest idx), 8 nodes/block ----------------
__global__ void __launch_bounds__(256)
topk_kernel(const float* __restrict__ G) {
    int warp = threadIdx.x >> 5, lane = threadIdx.x & 31;
    int node = blockIdx.x * 8 + warp;
    int b = node / NPTS, i = node - b * NPTS, base = b * NPTS;
    const float* Grow = G + ((size_t)b * NPTS + i) * NPTS;
    float sqi = g_sq[node];

    float val[8]; int idx[8];
    #pragma unroll
    for (int q = 0; q < 8; q++) { val[q] = 3.3e38f; idx[q] = 0x7FFFFFFF; }

    for (int j = lane; j < NPTS; j += 32) {
        float v = sqi + g_sq[base + j] - 2.f * Grow[j];
        bool lt = (v < val[7]) || (v == val[7] && j < idx[7]);
        if (lt) {
            val[7] = v; idx[7] = j;
            #pragma unroll
            for (int q = 7; q > 0; q--) {
                bool sw = (val[q] < val[q - 1]) ||
                          (val[q] == val[q - 1] && idx[q] < idx[q - 1]);
                if (sw) {
                    float tv = val[q]; val[q] = val[q - 1]; val[q - 1] = tv;
                    int ti = idx[q]; idx[q] = idx[q - 1]; idx[q - 1] = ti;
                }
            }
        }
    }

    // 8 pop-min rounds across the warp (lexicographic on (value, index))
    #pragma unroll
    for (int kk = 0; kk < KNN; kk++) {
        float bv = val[0]; int bi = idx[0];
        #pragma unroll
        for (int o = 16; o; o >>= 1) {
            float ov = __shfl_xor_sync(0xFFFFFFFFu, bv, o);
            int   oi = __shfl_xor_sync(0xFFFFFFFFu, bi, o);
            if (ov < bv || (ov == bv && oi < bi)) { bv = ov; bi = oi; }
        }
        if (lane == 0) g_idx[node * KNN + kk] = base + bi;
        if (idx[0] == bi && val[0] == bv) {   // unique owner (indices unique)
            #pragma unroll
            for (int q = 0; q < 7; q++) { val[q] = val[q + 1]; idx[q] = idx[q + 1]; }
            val[7] = 3.3e38f; idx[7] = 0x7FFFFFFF;
        }
    }
}

// ---------------- fused edge GEMM: A=relu(U[i]+V[j]+b1) on the fly, max-over-k epilogue ----
__global__ void __launch_bounds__(256)
fused_edge_gemm(const float* __restrict__ U, const float* __restrict__ V,
                const float* __restrict__ b1, const float* __restrict__ W2,
                const float* __restrict__ b2, float* __restrict__ out,
                int ldo, int H, int H2) {
    __shared__ __align__(16) float As[16][132];
    __shared__ __align__(16) float Bs[16][132];
    int tid = threadIdx.x;
    int m0 = blockIdx.x * 128, n0 = blockIdx.y * 128;
    int tx = tid & 15, ty = tid >> 4;
    ull acc2[8][4];
    #pragma unroll
    for (int r = 0; r < 8; r++)
        #pragma unroll
        for (int q = 0; q < 4; q++) acc2[r][q] = 0ull;

    int arow = tid >> 1, ak8 = (tid & 1) * 8;
    int e = m0 + arow;
    const float* Urow = U + (size_t)(e >> 3) * H;
    const float* Vrow = V + (size_t)g_idx[e] * H;
    int bk = tid >> 4, bn8 = (tid & 15) * 8;

    for (int k0 = 0; k0 < H; k0 += 16) {
        {
            float4 u0 = *(const float4*)&Urow[k0 + ak8];
            float4 u1 = *(const float4*)&Urow[k0 + ak8 + 4];
            float4 v0 = *(const float4*)&Vrow[k0 + ak8];
            float4 v1 = *(const float4*)&Vrow[k0 + ak8 + 4];
            float4 c0 = *(const float4*)&b1[k0 + ak8];
            float4 c1 = *(const float4*)&b1[k0 + ak8 + 4];
            As[ak8 + 0][arow] = fmaxf(u0.x + v0.x + c0.x, 0.f);
            As[ak8 + 1][arow] = fmaxf(u0.y + v0.y + c0.y, 0.f);
            As[ak8 + 2][arow] = fmaxf(u0.z + v0.z + c0.z, 0.f);
            As[ak8 + 3][arow] = fmaxf(u0.w + v0.w + c0.w, 0.f);
            As[ak8 + 4][arow] = fmaxf(u1.x + v1.x + c1.x, 0.f);
            As[ak8 + 5][arow] = fmaxf(u1.y + v1.y + c1.y, 0.f);
            As[ak8 + 6][arow] = fmaxf(u1.z + v1.z + c1.z, 0.f);
            As[ak8 + 7][arow] = fmaxf(u1.w + v1.w + c1.w, 0.f);
        }
        if (n0 + bn8 + 7 < H2) {
            float4 w0 = *(const float4*)&W2[(size_t)(k0 + bk) * H2 + n0 + bn8];
            float4 w1 = *(const float4*)&W2[(size_t)(k0 + bk) * H2 + n0 + bn8 + 4];
            Bs[bk][bn8 + 0] = w0.x; Bs[bk][bn8 + 1] = w0.y;
            Bs[bk][bn8 + 2] = w0.z; Bs[bk][bn8 + 3] = w0.w;
            Bs[bk][bn8 + 4] = w1.x; Bs[bk][bn8 + 5] = w1.y;
            Bs[bk][bn8 + 6] = w1.z; Bs[bk][bn8 + 7] = w1.w;
        } else {
            #pragma unroll
            for (int q = 0; q < 8; q++) {
                int n = n0 + bn8 + q;
                Bs[bk][bn8 + q] = (n < H2) ? W2[(size_t)(k0 + bk) * H2 + n] : 0.f;
            }
        }
        __syncthreads();
        #pragma unroll
        for (int kk = 0; kk < 16; kk++) {
            float a[8];
            *(float4*)&a[0] = *(const float4*)&As[kk][ty * 8];
            *(float4*)&a[4] = *(const float4*)&As[kk][ty * 8 + 4];
            ull bp[4];
            {
                ulonglong2 t0 = *(const ulonglong2*)&Bs[kk][tx * 8];
                ulonglong2 t1 = *(const ulonglong2*)&Bs[kk][tx * 8 + 4];
                bp[0] = t0.x; bp[1] = t0.y; bp[2] = t1.x; bp[3] = t1.y;
            }
            #pragma unroll
            for (int r = 0; r < 8; r++) {
                ull ap = pk2(a[r]);
                #pragma unroll
                for (int q = 0; q < 4; q++) fma2(acc2[r][q], ap, bp[q]);
            }
        }
        __syncthreads();
    }

    int node = (m0 >> 3) + ty;
    float av[8][8];
    #pragma unroll
    for (int r = 0; r < 8; r++)
        #pragma unroll
        for (int q = 0; q < 4; q++) unpk(acc2[r][q], av[r][2 * q], av[r][2 * q + 1]);
    #pragma unroll
    for (int c = 0; c < 8; c++) {
        int n = n0 + tx * 8 + c;
        if (n >= H2) continue;
        float m = av[0][c];
        #pragma unroll
        for (int r = 1; r < 8; r++) m = fmaxf(m, av[r][c]);
        out[(size_t)node * ldo + n] = m + b2[n];
    }
}

// ---------------- generic fp32 GEMM (64x64, 4x4, f32x2): C = A @ B (+bias)(+relu) -------
__global__ void __launch_bounds__(256)
gemm_kernel(const float* __restrict__ A, int lda,
            const float* __restrict__ B, int ldb,
            float* __restrict__ C, int ldc,
            int M, int N, int K,
            const float* __restrict__ bias, int dorelu) {
    __shared__ __align__(16) float As[16][68];
    __shared__ __align__(16) float Bs[16][68];
    int tid = threadIdx.x;
    int tx = tid & 15, ty = tid >> 4;
    int m0 = blockIdx.x * 64, n0 = blockIdx.y * 64;
    ull acc2[4][2];
    #pragma unroll
    for (int r = 0; r < 4; r++) { acc2[r][0] = 0ull; acc2[r][1] = 0ull; }

    int la_m = tid >> 2;
    int la_k = (tid & 3) << 2;
    int lb_k = tid >> 4;
    int lb_n = (tid & 15) << 2;

    for (int k0 = 0; k0 < K; k0 += 16) {
        int am = m0 + la_m;
        #pragma unroll
        for (int q = 0; q < 4; q++) {
            int ak = k0 + la_k + q;
            As[la_k + q][la_m] = (am < M && ak < K) ? A[(size_t)am * lda + ak] : 0.f;
        }
        int bk = k0 + lb_k;
        #pragma unroll
        for (int q = 0; q < 4; q++) {
            int bn = n0 + lb_n + q;
            Bs[lb_k][lb_n + q] = (bk < K && bn < N) ? B[(size_t)bk * ldb + bn] : 0.f;
        }
        __syncthreads();
        #pragma unroll
        for (int kk = 0; kk < 16; kk++) {
            float4 af = *(const float4*)&As[kk][ty << 2];
            ulonglong2 bt = *(const ulonglong2*)&Bs[kk][tx << 2];
            float a[4] = {af.x, af.y, af.z, af.w};
            #pragma unroll
            for (int r = 0; r < 4; r++) {
                ull ap = pk2(a[r]);
                fma2(acc2[r][0], ap, bt.x);
                fma2(acc2[r][1], ap, bt.y);
            }
        }
        __syncthreads();
    }

    #pragma unroll
    for (int r = 0; r < 4; r++) {
        int m = m0 + (ty << 2) + r;
        if (m >= M) continue;
        float av[4];
        unpk(acc2[r][0], av[0], av[1]);
        unpk(acc2[r][1], av[2], av[3]);
        #pragma unroll
        for (int c = 0; c < 4; c++) {
            int n = n0 + (tx << 2) + c;
            if (n >= N) continue;
            float v = av[c];
            if (bias) v += bias[n];
            if (dorelu) v = fmaxf(v, 0.f);
            C[(size_t)m * ldc + n] = v;
        }
    }
}

// ---------------- dual GEMM (standalone, for hi/hjg): U = A@B1, V = A@B2 ---------------
__global__ void __launch_bounds__(256)
gemm_uv_kernel(const float* __restrict__ A, int lda,
               const float* __restrict__ B1, const float* __restrict__ B2, int ldb,
               float* __restrict__ Uo, float* __restrict__ Vo, int ldu,
               int M, int N, int K) {
    __shared__ __align__(16) float As[16][68];
    __shared__ __align__(16) float B1s[16][68];
    __shared__ __align__(16) float B2s[16][68];
    int tid = threadIdx.x;
    int tx = tid & 15, ty = tid >> 4;
    int m0 = blockIdx.x * 64, n0 = blockIdx.y * 64;
    ull aU[4][2], aV[4][2];
    #pragma unroll
    for (int r = 0; r < 4; r++) {
        aU[r][0] = aU[r][1] = 0ull;
        aV[r][0] = aV[r][1] = 0ull;
    }
    int la_m = tid >> 2;
    int la_k = (tid & 3) << 2;
    int lb_k = tid >> 4;
    int lb_n = (tid & 15) << 2;

    for (int k0 = 0; k0 < K; k0 += 16) {
        int am = m0 + la_m;
        #pragma unroll
        for (int q = 0; q < 4; q++) {
            int ak = k0 + la_k + q;
            As[(la_k + q)][la_m] = (am < M && ak < K) ? A[(size_t)am * lda + ak] : 0.f;
        }
        int bk = k0 + lb_k;
        #pragma unroll
        for (int q = 0; q < 4; q++) {
            int bn = n0 + lb_n + q;
            float v1 = 0.f, v2 = 0.f;
            if (bk < K && bn < N) {
                size_t o = (size_t)bk * ldb + bn;
                v1 = B1[o]; v2 = B2[o];
            }
            B1s[lb_k][lb_n + q] = v1;
            B2s[lb_k][lb_n + q] = v2;
        }
        __syncthreads();
        #pragma unroll
        for (int kk = 0; kk < 16; kk++) {
            float4 af = *(const float4*)&As[kk][ty << 2];
            ulonglong2 b1t = *(const ulonglong2*)&B1s[kk][tx << 2];
            ulonglong2 b2t = *(const ulonglong2*)&B2s[kk][tx << 2];
            float a[4] = {af.x, af.y, af.z, af.w};
            #pragma unroll
            for (int r = 0; r < 4; r++) {
                ull ap = pk2(a[r]);
                fma2(aU[r][0], ap, b1t.x);
                fma2(aU[r][1], ap, b1t.y);
                fma2(aV[r][0], ap, b2t.x);
                fma2(aV[r][1], ap, b2t.y);
            }
        }
        __syncthreads();
    }

    #pragma unroll
    for (int r = 0; r < 4; r++) {
        int m = m0 + (ty << 2) + r;
        if (m >= M) continue;
        float u[4], v[4];
        unpk(aU[r][0], u[0], u[1]); unpk(aU[r][1], u[2], u[3]);
        unpk(aV[r][0], v[0], v[1]); unpk(aV[r][1], v[2], v[3]);
        #pragma unroll
        for (int c = 0; c < 4; c++) {
            int n = n0 + (tx << 2) + c;
            if (n >= N) continue;
            Uo[(size_t)m * ldu + n] = u[c];
            Vo[(size_t)m * ldu + n] = v[c];
        }
    }
}

// ---------------- fused global max pool + hg ----------------
__global__ void gmaxhg_kernel(const float* __restrict__ w1, const float* __restrict__ b1) {
    __shared__ float sg[128];
    int b = blockIdx.x, c = threadIdx.x;
    const float* p = g_sf + (size_t)b * NPTS * 128 + c;
    float m = -3.3e38f;
    #pragma unroll 4
    for (int n = 0; n < NPTS; n++) m = fmaxf(m, p[n * 128]);
    sg[c] = m;
    __syncthreads();
    float s = b1[c];
    #pragma unroll 4
    for (int d = 0; d < 128; d++) s += sg[d] * w1[(256 + d) * 128 + c];
    g_hg[b * 128 + c] = s;
}

// ---------------- pair kernel: 64x64 tile, 4x4 pairs/thread, fused relu+dot+sigmoid ----
__global__ void __launch_bounds__(256)
pair_kernel(const float* __restrict__ w2, const float* __restrict__ b2,
            float* __restrict__ out) {
    int bx = blockIdx.x, by = blockIdx.y;   // bx = j tile, by = i tile
    if (bx < by) return;
    int b = blockIdx.z;
    extern __shared__ float ps[];
    float* s_hi = ps;                 // 64 x 132
    float* s_hj = ps + 64 * 132;      // 64 x 132
    float* s_w  = ps + 2 * 64 * 132;  // 128

    int tid = threadIdx.y * 16 + threadIdx.x;
    int bi0 = by * 64, bj0 = bx * 64;

    for (int t = tid; t < 64 * 32; t += 256) {
        int r = t >> 5, c4 = (t & 31) << 2;
        int gi = bi0 + r;
        float4 v = make_float4(0.f, 0.f, 0.f, 0.f);
        if (gi < NPTS) v = *(const float4*)&g_hi[((size_t)(b * NPTS + gi)) * 128 + c4];
        *(float4*)&s_hi[r * 132 + c4] = v;
        int gj = bj0 + r;
        float4 u = make_float4(0.f, 0.f, 0.f, 0.f);
        if (gj < NPTS) {
            u = *(const float4*)&g_hjg[((size_t)(b * NPTS + gj)) * 128 + c4];
            float4 hgv = *(const float4*)&g_hg[b * 128 + c4];
            u.x += hgv.x; u.y += hgv.y; u.z += hgv.z; u.w += hgv.w;
        }
        *(float4*)&s_hj[r * 132 + c4] = u;
    }
    if (tid < 32) *(float4*)&s_w[tid * 4] = *(const float4*)&w2[tid * 4];
    __syncthreads();

    int ri0 = threadIdx.y * 4, cj0 = threadIdx.x * 4;
    float acc[4][4] = {};
    for (int c4 = 0; c4 < 128; c4 += 4) {
        float4 w = *(const float4*)&s_w[c4];
        float4 A[4], H[4];
        #pragma unroll
        for (int r = 0; r < 4; r++) A[r] = *(const float4*)&s_hi[(ri0 + r) * 132 + c4];
        #pragma unroll
        for (int c = 0; c < 4; c++) H[c] = *(const float4*)&s_hj[(cj0 + c) * 132 + c4];
        #pragma unroll
        for (int r = 0; r < 4; r++)
            #pragma unroll
            for (int c = 0; c < 4; c++) {
                acc[r][c] += fmaxf(A[r].x + H[c].x, 0.f) * w.x
                           + fmaxf(A[r].y + H[c].y, 0.f) * w.y
                           + fmaxf(A[r].z + H[c].z, 0.f) * w.z
                           + fmaxf(A[r].w + H[c].w, 0.f) * w.w;
            }
    }

    float bias2 = b2[0];
    #pragma unroll
    for (int r = 0; r < 4; r++) {
        int gi = bi0 + ri0 + r;
        #pragma unroll
        for (int c = 0; c < 4; c++) {
            int gj = bj0 + cj0 + c;
            if (gj < NPTS && gi < gj) {
                float m = acc[r][c] + bias2;
                int p = gi * (NPTS - 1) - (gi * (gi - 1)) / 2 + (gj - gi - 1);
                int off = b * NPAIR + p;
                out[off] = 1.f / (1.f + __expf(-m));
                out[BATCH * NPAIR + off] = m;
            }
        }
    }
}

// ============================ host side ============================
static void* sym_addr(const void* s) {
    void* p = nullptr;
    cudaGetSymbolAddress(&p, s);
    return p;
}

static void gemm(const float* A, int lda, const float* B, int ldb,
                 float* C, int ldc, int M, int N, int K,
                 const float* bias, int dorelu) {
    dim3 g((M + 63) / 64, (N + 63) / 64);
    gemm_kernel<<<g, 256>>>(A, lda, B, ldb, C, ldc, M, N, K, bias, dorelu);
}

static void edge_conv(const float* x, int lda, int C, int H, int H2,
                      const float* w1, const float* b1,
                      const float* w2, const float* b2,
                      float* U, float* V, float* G,
                      float* outp, int ldo) {
    int nuvn = (H + 63) / 64;
    prep_kernel<<<128 + 32 * nuvn, 256>>>(x, lda, C, H, w1, G, U, V);
    topk_kernel<<<BNODES / 8, 256>>>(G);
    fused_edge_gemm<<<dim3(125, (H2 + 127) / 128), 256>>>(U, V, b1, w2, b2, outp, ldo, H, H2);
}

extern "C" void kernel_launch(void* const* d_in, const int* in_sizes, int n_in,
                              void* d_out, int out_size) {
    const float* in[21];
    for (int i = 0; i < 21; i++) in[i] = (const float*)d_in[i];
    const float* pos   = in[0];
    const float* c1_w1 = in[1];  const float* c1_b1 = in[2];
    const float* c1_w2 = in[3];  const float* c1_b2 = in[4];
    const float* c2_w1 = in[5];  const float* c2_b1 = in[6];
    const float* c2_w2 = in[7];  const float* c2_b2 = in[8];
    const float* c3_w1 = in[9];  const float* c3_b1 = in[10];
    const float* c3_w2 = in[11]; const float* c3_b2 = in[12];
    const float* sm_w1 = in[13]; const float* sm_b1 = in[14];
    const float* sm_w2 = in[15]; const float* sm_b2 = in[16];
    const float* ec_w1 = in[17]; const float* ec_b1 = in[18];
    const float* ec_w2 = in[19]; const float* ec_b2 = in[20];

    float* U   = (float*)sym_addr(g_U);
    float* V   = (float*)sym_addr(g_V);
    float* G   = (float*)sym_addr(g_G);
    float* cat = (float*)sym_addr(g_cat);
    float* smh = (float*)sym_addr(g_smh);
    float* sf  = (float*)sym_addr(g_sf);
    float* hi  = (float*)sym_addr(g_hi);
    float* hjg = (float*)sym_addr(g_hjg);

    // conv1: pos[2000,3] -> x1 at cat+0 (32 ch)
    edge_conv(pos, 3, 3, 16, 32, c1_w1, c1_b1, c1_w2, c1_b2, U, V, G, cat + 0, 672);
    // conv2: x1 -> x2 at cat+32 (128 ch)
    edge_conv(cat + 0, 672, 32, 64, 128, c2_w1, c2_b1, c2_w2, c2_b2, U, V, G, cat + 32, 672);
    // conv3: x2 -> x3 at cat+160 (512 ch)
    edge_conv(cat + 32, 672, 128, 256, 512, c3_w1, c3_b1, c3_w2, c3_b2, U, V, G, cat + 160, 672);

    // sm MLP: [2000,672] -> relu 256 -> 128
    gemm(cat, 672, sm_w1, 256, smh, 256, BNODES, 256, 672, sm_b1, 1);
    gemm(smh, 256, sm_w2, 128, sf, 128, BNODES, 128, 256, sm_b2, 0);

    // fused global max pool + hg
    gmaxhg_kernel<<<BATCH, 128>>>(ec_w1, ec_b1);

    // hjg = sf @ ec_w1[128:256] ; hi = sf @ ec_w1[:128]  (one dual launch)
    dim3 ghh((BNODES + 63) / 64, 2);
    gemm_uv_kernel<<<ghh, 256>>>(sf, 128, ec_w1 + 128 * 128, ec_w1, 128,
                                 hjg, hi, 128, BNODES, 128, 128);

    // fused pair stage -> d_out = [pair_prob (B*P), mlp_out (B*P)]
    size_t psmem = (2 * 64 * 132 + 128) * sizeof(float);
    cudaFuncSetAttribute(pair_kernel, cudaFuncAttributeMaxDynamicSharedMemorySize, (int)psmem);
    pair_kernel<<<dim3(16, 16, BATCH), dim3(16, 16), psmem>>>(ec_w2, ec_b2, (float*)d_out);
}

// round 6
// speedup vs baseline: 1.0335x; 1.0335x over previous
#include <cuda_runtime.h>
#include <math.h>

#define NPTS   1000
#define BATCH  2
#define BNODES 2000
#define KNN    8
#define NEDGE  (BNODES*KNN)
#define NPAIR  499500   // NPTS*(NPTS-1)/2

typedef unsigned long long ull;

// packed f32x2 helpers (Blackwell: fma.rn.f32x2 — PTX-only)
__device__ __forceinline__ ull pk2(float x) {
    ull r; asm("mov.b64 %0, {%1, %1};" : "=l"(r) : "f"(x)); return r;
}
__device__ __forceinline__ void fma2(ull& d, ull a, ull b) {
    asm("fma.rn.f32x2 %0, %1, %2, %0;" : "+l"(d) : "l"(a), "l"(b));
}
__device__ __forceinline__ void unpk(ull v, float& lo, float& hi) {
    asm("mov.b64 {%0, %1}, %2;" : "=f"(lo), "=f"(hi) : "l"(v));
}

// ---------------- scratch (static __device__; no allocations) ----------------
__device__ float g_sq[BNODES];
__device__ int   g_idx[NEDGE];
__device__ __align__(16) float g_x1[BNODES*32];
__device__ __align__(16) float g_x2[BNODES*128];
__device__ __align__(16) float g_U[BNODES*256];
__device__ __align__(16) float g_V[BNODES*256];
__device__ __align__(16) float g_G[BATCH*NPTS*NPTS];
__device__ __align__(16) float g_cat[BNODES*672];
__device__ __align__(16) float g_smh[BNODES*256];
__device__ __align__(16) float g_sf[BNODES*128];
__device__ __align__(16) float g_hi[BNODES*128];
__device__ __align__(16) float g_hjg[BNODES*128];
__device__ __align__(16) float g_hg[BATCH*128];

// ---------------- X @ X^T per batch: 128x128 tile, 8x8/thread, double-buffered --------
__global__ void __launch_bounds__(256, 2)
xxt_kernel(const float* __restrict__ x, int lda, int C, float* __restrict__ G) {
    __shared__ __align__(16) float As[2][16 * 132];
    __shared__ __align__(16) float Bs[2][16 * 132];
    int b  = blockIdx.z;
    int m0 = blockIdx.y * 128, n0 = blockIdx.x * 128;
    const float* xb = x + (size_t)b * NPTS * lda;
    int tid  = threadIdx.x;
    int lrow = tid >> 1, lk8 = (tid & 1) * 8;
    int tx = tid & 15, ty = tid >> 4;
    ull acc2[8][4];
    #pragma unroll
    for (int r = 0; r < 8; r++)
        #pragma unroll
        for (int q = 0; q < 4; q++) acc2[r][q] = 0ull;

    int ar = m0 + lrow, br = n0 + lrow;
    float ra[8], rb[8];
    #pragma unroll
    for (int q = 0; q < 8; q++) {
        int k = lk8 + q;
        ra[q] = (ar < NPTS && k < C) ? xb[(size_t)ar * lda + k] : 0.f;
        rb[q] = (br < NPTS && k < C) ? xb[(size_t)br * lda + k] : 0.f;
    }
    #pragma unroll
    for (int q = 0; q < 8; q++) {
        As[0][(lk8 + q) * 132 + lrow] = ra[q];
        Bs[0][(lk8 + q) * 132 + lrow] = rb[q];
    }
    __syncthreads();

    int buf = 0;
    for (int k0 = 0; k0 < C; k0 += 16) {
        int nk = k0 + 16;
        if (nk < C) {
            #pragma unroll
            for (int q = 0; q < 8; q++) {
                int k = nk + lk8 + q;
                ra[q] = (ar < NPTS && k < C) ? xb[(size_t)ar * lda + k] : 0.f;
                rb[q] = (br < NPTS && k < C) ? xb[(size_t)br * lda + k] : 0.f;
            }
        }
        const float* Ab = As[buf];
        const float* Bb = Bs[buf];
        #pragma unroll
        for (int kk = 0; kk < 16; kk++) {
            float a[8];
            *(float4*)&a[0] = *(const float4*)&Ab[kk * 132 + ty * 8];
            *(float4*)&a[4] = *(const float4*)&Ab[kk * 132 + ty * 8 + 4];
            ull bp[4];
            {
                ulonglong2 t0 = *(const ulonglong2*)&Bb[kk * 132 + tx * 8];
                ulonglong2 t1 = *(const ulonglong2*)&Bb[kk * 132 + tx * 8 + 4];
                bp[0] = t0.x; bp[1] = t0.y; bp[2] = t1.x; bp[3] = t1.y;
            }
            #pragma unroll
            for (int r = 0; r < 8; r++) {
                ull ap = pk2(a[r]);
                #pragma unroll
                for (int q = 0; q < 4; q++) fma2(acc2[r][q], ap, bp[q]);
            }
        }
        if (nk < C) {
            int nb = buf ^ 1;
            #pragma unroll
            for (int q = 0; q < 8; q++) {
                As[nb][(lk8 + q) * 132 + lrow] = ra[q];
                Bs[nb][(lk8 + q) * 132 + lrow] = rb[q];
            }
            __syncthreads();
            buf = nb;
        }
    }
    #pragma unroll
    for (int r = 0; r < 8; r++) {
        int i = m0 + ty * 8 + r;
        if (i >= NPTS) continue;
        float av[8];
        #pragma unroll
        for (int q = 0; q < 4; q++) unpk(acc2[r][q], av[2 * q], av[2 * q + 1]);
        #pragma unroll
        for (int c = 0; c < 8; c++) {
            int j = n0 + tx * 8 + c;
            if (j < NPTS) {
                G[((size_t)b * NPTS + i) * NPTS + j] = av[c];
                if (i == j) g_sq[b * NPTS + i] = av[c];
            }
        }
    }
}

// ---------------- warp-parallel top-8 (ties -> lowest idx), 8 nodes/block --------------
__global__ void __launch_bounds__(256)
topk_kernel(const float* __restrict__ G) {
    int warp = threadIdx.x >> 5, lane = threadIdx.x & 31;
    int node = blockIdx.x * 8 + warp;
    int b = node / NPTS, i = node - b * NPTS, base = b * NPTS;
    const float* Grow = G + ((size_t)b * NPTS + i) * NPTS;
    float sqi = g_sq[node];

    float val[8]; int idx[8];
    #pragma unroll
    for (int q = 0; q < 8; q++) { val[q] = 3.3e38f; idx[q] = 0x7FFFFFFF; }

    for (int j = lane; j < NPTS; j += 32) {
        float v = sqi + g_sq[base + j] - 2.f * Grow[j];
        bool lt = (v < val[7]) || (v == val[7] && j < idx[7]);
        if (lt) {
            val[7] = v; idx[7] = j;
            #pragma unroll
            for (int q = 7; q > 0; q--) {
                bool sw = (val[q] < val[q - 1]) ||
                          (val[q] == val[q - 1] && idx[q] < idx[q - 1]);
                if (sw) {
                    float tv = val[q]; val[q] = val[q - 1]; val[q - 1] = tv;
                    int ti = idx[q]; idx[q] = idx[q - 1]; idx[q - 1] = ti;
                }
            }
        }
    }

    #pragma unroll
    for (int kk = 0; kk < KNN; kk++) {
        float bv = val[0]; int bi = idx[0];
        #pragma unroll
        for (int o = 16; o; o >>= 1) {
            float ov = __shfl_xor_sync(0xFFFFFFFFu, bv, o);
            int   oi = __shfl_xor_sync(0xFFFFFFFFu, bi, o);
            if (ov < bv || (ov == bv && oi < bi)) { bv = ov; bi = oi; }
        }
        if (lane == 0) g_idx[node * KNN + kk] = base + bi;
        if (idx[0] == bi && val[0] == bv) {
            #pragma unroll
            for (int q = 0; q < 7; q++) { val[q] = val[q + 1]; idx[q] = idx[q + 1]; }
            val[7] = 3.3e38f; idx[7] = 0x7FFFFFFF;
        }
    }
}

// -------- fused edge GEMM: A=relu(U[i]+V[j]+b1) on the fly, double-buffered ------------
__global__ void __launch_bounds__(256, 2)
fused_edge_gemm(const float* __restrict__ U, const float* __restrict__ V,
                const float* __restrict__ b1, const float* __restrict__ W2,
                const float* __restrict__ b2, float* __restrict__ out,
                int ldo, float* __restrict__ outc, int H, int H2) {
    __shared__ __align__(16) float As[2][16 * 132];
    __shared__ __align__(16) float Bs[2][16 * 132];
    __shared__ float sb1[256];
    int tid = threadIdx.x;
    int m0 = blockIdx.x * 128, n0 = blockIdx.y * 128;
    int tx = tid & 15, ty = tid >> 4;
    if (tid < H) sb1[tid] = b1[tid];
    ull acc2[8][4];
    #pragma unroll
    for (int r = 0; r < 8; r++)
        #pragma unroll
        for (int q = 0; q < 4; q++) acc2[r][q] = 0ull;

    int arow = tid >> 1, ak8 = (tid & 1) * 8;
    int e = m0 + arow;
    const float* Urow = U + (size_t)(e >> 3) * H;
    const float* Vrow = V + (size_t)g_idx[e] * H;
    int bk = tid >> 4, bn8 = (tid & 15) * 8;

    float ru[8], rv[8], rb[8];
    // prefetch tile 0
    {
        float4 u0 = *(const float4*)&Urow[ak8];
        float4 u1 = *(const float4*)&Urow[ak8 + 4];
        float4 v0 = *(const float4*)&Vrow[ak8];
        float4 v1 = *(const float4*)&Vrow[ak8 + 4];
        ru[0] = u0.x; ru[1] = u0.y; ru[2] = u0.z; ru[3] = u0.w;
        ru[4] = u1.x; ru[5] = u1.y; ru[6] = u1.z; ru[7] = u1.w;
        rv[0] = v0.x; rv[1] = v0.y; rv[2] = v0.z; rv[3] = v0.w;
        rv[4] = v1.x; rv[5] = v1.y; rv[6] = v1.z; rv[7] = v1.w;
        if (n0 + bn8 + 7 < H2) {
            float4 w0 = *(const float4*)&W2[(size_t)bk * H2 + n0 + bn8];
            float4 w1 = *(const float4*)&W2[(size_t)bk * H2 + n0 + bn8 + 4];
            rb[0] = w0.x; rb[1] = w0.y; rb[2] = w0.z; rb[3] = w0.w;
            rb[4] = w1.x; rb[5] = w1.y; rb[6] = w1.z; rb[7] = w1.w;
        } else {
            #pragma unroll
            for (int q = 0; q < 8; q++) {
                int n = n0 + bn8 + q;
                rb[q] = (n < H2) ? W2[(size_t)bk * H2 + n] : 0.f;
            }
        }
    }
    __syncthreads();   // sb1 ready
    #pragma unroll
    for (int q = 0; q < 8; q++) {
        As[0][(ak8 + q) * 132 + arow] = fmaxf(ru[q] + rv[q] + sb1[ak8 + q], 0.f);
        Bs[0][bk * 132 + bn8 + q] = rb[q];
    }
    __syncthreads();

    int buf = 0;
    for (int k0 = 0; k0 < H; k0 += 16) {
        int nk = k0 + 16;
        if (nk < H) {
            float4 u0 = *(const float4*)&Urow[nk + ak8];
            float4 u1 = *(const float4*)&Urow[nk + ak8 + 4];
            float4 v0 = *(const float4*)&Vrow[nk + ak8];
            float4 v1 = *(const float4*)&Vrow[nk + ak8 + 4];
            ru[0] = u0.x; ru[1] = u0.y; ru[2] = u0.z; ru[3] = u0.w;
            ru[4] = u1.x; ru[5] = u1.y; ru[6] = u1.z; ru[7] = u1.w;
            rv[0] = v0.x; rv[1] = v0.y; rv[2] = v0.z; rv[3] = v0.w;
            rv[4] = v1.x; rv[5] = v1.y; rv[6] = v1.z; rv[7] = v1.w;
            if (n0 + bn8 + 7 < H2) {
                float4 w0 = *(const float4*)&W2[(size_t)(nk + bk) * H2 + n0 + bn8];
                float4 w1 = *(const float4*)&W2[(size_t)(nk + bk) * H2 + n0 + bn8 + 4];
                rb[0] = w0.x; rb[1] = w0.y; rb[2] = w0.z; rb[3] = w0.w;
                rb[4] = w1.x; rb[5] = w1.y; rb[6] = w1.z; rb[7] = w1.w;
            } else {
                #pragma unroll
                for (int q = 0; q < 8; q++) {
                    int n = n0 + bn8 + q;
                    rb[q] = (n < H2) ? W2[(size_t)(nk + bk) * H2 + n] : 0.f;
                }
            }
        }
        const float* Ab = As[buf];
        const float* Bb = Bs[buf];
        #pragma unroll
        for (int kk = 0; kk < 16; kk++) {
            float a[8];
            *(float4*)&a[0] = *(const float4*)&Ab[kk * 132 + ty * 8];
            *(float4*)&a[4] = *(const float4*)&Ab[kk * 132 + ty * 8 + 4];
            ull bp[4];
            {
                ulonglong2 t0 = *(const ulonglong2*)&Bb[kk * 132 + tx * 8];
                ulonglong2 t1 = *(const ulonglong2*)&Bb[kk * 132 + tx * 8 + 4];
                bp[0] = t0.x; bp[1] = t0.y; bp[2] = t1.x; bp[3] = t1.y;
            }
            #pragma unroll
            for (int r = 0; r < 8; r++) {
                ull ap = pk2(a[r]);
                #pragma unroll
                for (int q = 0; q < 4; q++) fma2(acc2[r][q], ap, bp[q]);
            }
        }
        if (nk < H) {
            int nb = buf ^ 1;
            #pragma unroll
            for (int q = 0; q < 8; q++) {
                As[nb][(ak8 + q) * 132 + arow] = fmaxf(ru[q] + rv[q] + sb1[nk + ak8 + q], 0.f);
                Bs[nb][bk * 132 + bn8 + q] = rb[q];
            }
            __syncthreads();
            buf = nb;
        }
    }

    int node = (m0 >> 3) + ty;
    float av[8][8];
    #pragma unroll
    for (int r = 0; r < 8; r++)
        #pragma unroll
        for (int q = 0; q < 4; q++) unpk(acc2[r][q], av[r][2 * q], av[r][2 * q + 1]);
    #pragma unroll
    for (int c = 0; c < 8; c++) {
        int n = n0 + tx * 8 + c;
        if (n >= H2) continue;
        float m = av[0][c];
        #pragma unroll
        for (int r = 1; r < 8; r++) m = fmaxf(m, av[r][c]);
        m += b2[n];
        out[(size_t)node * ldo + n] = m;
        if (outc) outc[(size_t)node * H2 + n] = m;
    }
}

// ------------- generic fp32 GEMM (64x64, 4x4, f32x2, double-buffered) ------------------
__global__ void __launch_bounds__(256, 2)
gemm_kernel(const float* __restrict__ A, int lda,
            const float* __restrict__ B, int ldb,
            float* __restrict__ C, int ldc,
            int M, int N, int K,
            const float* __restrict__ bias, int dorelu) {
    __shared__ __align__(16) float As[2][16 * 68];
    __shared__ __align__(16) float Bs[2][16 * 68];
    int tid = threadIdx.x;
    int tx = tid & 15, ty = tid >> 4;
    int m0 = blockIdx.x * 64, n0 = blockIdx.y * 64;
    ull acc2[4][2];
    #pragma unroll
    for (int r = 0; r < 4; r++) { acc2[r][0] = 0ull; acc2[r][1] = 0ull; }

    int la_m = tid >> 2;
    int la_k = (tid & 3) << 2;
    int lb_k = tid >> 4;
    int lb_n = (tid & 15) << 2;
    int am = m0 + la_m;

    float ra[4], rbv[4];
    #pragma unroll
    for (int q = 0; q < 4; q++) {
        int ak = la_k + q;
        ra[q] = (am < M && ak < K) ? A[(size_t)am * lda + ak] : 0.f;
        int bn = n0 + lb_n + q;
        rbv[q] = (lb_k < K && bn < N) ? B[(size_t)lb_k * ldb + bn] : 0.f;
    }
    #pragma unroll
    for (int q = 0; q < 4; q++) {
        As[0][(la_k + q) * 68 + la_m] = ra[q];
        Bs[0][lb_k * 68 + lb_n + q] = rbv[q];
    }
    __syncthreads();

    int buf = 0;
    for (int k0 = 0; k0 < K; k0 += 16) {
        int nk = k0 + 16;
        if (nk < K) {
            #pragma unroll
            for (int q = 0; q < 4; q++) {
                int ak = nk + la_k + q;
                ra[q] = (am < M && ak < K) ? A[(size_t)am * lda + ak] : 0.f;
                int bn = n0 + lb_n + q;
                int bk = nk + lb_k;
                rbv[q] = (bk < K && bn < N) ? B[(size_t)bk * ldb + bn] : 0.f;
            }
        }
        const float* Ab = As[buf];
        const float* Bb = Bs[buf];
        #pragma unroll
        for (int kk = 0; kk < 16; kk++) {
            float4 af = *(const float4*)&Ab[kk * 68 + (ty << 2)];
            ulonglong2 bt = *(const ulonglong2*)&Bb[kk * 68 + (tx << 2)];
            float a[4] = {af.x, af.y, af.z, af.w};
            #pragma unroll
            for (int r = 0; r < 4; r++) {
                ull ap = pk2(a[r]);
                fma2(acc2[r][0], ap, bt.x);
                fma2(acc2[r][1], ap, bt.y);
            }
        }
        if (nk < K) {
            int nb = buf ^ 1;
            #pragma unroll
            for (int q = 0; q < 4; q++) {
                As[nb][(la_k + q) * 68 + la_m] = ra[q];
                Bs[nb][lb_k * 68 + lb_n + q] = rbv[q];
            }
            __syncthreads();
            buf = nb;
        }
    }

    #pragma unroll
    for (int r = 0; r < 4; r++) {
        int m = m0 + (ty << 2) + r;
        if (m >= M) continue;
        float av[4];
        unpk(acc2[r][0], av[0], av[1]);
        unpk(acc2[r][1], av[2], av[3]);
        #pragma unroll
        for (int c = 0; c < 4; c++) {
            int n = n0 + (tx << 2) + c;
            if (n >= N) continue;
            float v = av[c];
            if (bias) v += bias[n];
            if (dorelu) v = fmaxf(v, 0.f);
            C[(size_t)m * ldc + n] = v;
        }
    }
}

// ------------- dual GEMM (double-buffered): Uo = A@(B1 - sub*B2), Vo = A@B2 ------------
__global__ void __launch_bounds__(256, 2)
gemm_uv_kernel(const float* __restrict__ A, int lda,
               const float* __restrict__ B1, const float* __restrict__ B2, int ldb,
               float* __restrict__ Uo, float* __restrict__ Vo, int ldu,
               int M, int N, int K, int sub) {
    __shared__ __align__(16) float As[2][16 * 68];
    __shared__ __align__(16) float B1s[2][16 * 68];
    __shared__ __align__(16) float B2s[2][16 * 68];
    int tid = threadIdx.x;
    int tx = tid & 15, ty = tid >> 4;
    int m0 = blockIdx.x * 64, n0 = blockIdx.y * 64;
    ull aU[4][2], aV[4][2];
    #pragma unroll
    for (int r = 0; r < 4; r++) {
        aU[r][0] = aU[r][1] = 0ull;
        aV[r][0] = aV[r][1] = 0ull;
    }
    int la_m = tid >> 2;
    int la_k = (tid & 3) << 2;
    int lb_k = tid >> 4;
    int lb_n = (tid & 15) << 2;
    int am = m0 + la_m;

    float ra[4], r1[4], r2[4];
    #pragma unroll
    for (int q = 0; q < 4; q++) {
        int ak = la_k + q;
        ra[q] = (am < M && ak < K) ? A[(size_t)am * lda + ak] : 0.f;
        int bn = n0 + lb_n + q;
        float v1 = 0.f, v2 = 0.f;
        if (lb_k < K && bn < N) {
            size_t o = (size_t)lb_k * ldb + bn;
            v1 = B1[o]; v2 = B2[o];
        }
        r1[q] = sub ? (v1 - v2) : v1;
        r2[q] = v2;
    }
    #pragma unroll
    for (int q = 0; q < 4; q++) {
        As[0][(la_k + q) * 68 + la_m] = ra[q];
        B1s[0][lb_k * 68 + lb_n + q] = r1[q];
        B2s[0][lb_k * 68 + lb_n + q] = r2[q];
    }
    __syncthreads();

    int buf = 0;
    for (int k0 = 0; k0 < K; k0 += 16) {
        int nk = k0 + 16;
        if (nk < K) {
            #pragma unroll
            for (int q = 0; q < 4; q++) {
                int ak = nk + la_k + q;
                ra[q] = (am < M && ak < K) ? A[(size_t)am * lda + ak] : 0.f;
                int bn = n0 + lb_n + q;
                int bk = nk + lb_k;
                float v1 = 0.f, v2 = 0.f;
                if (bk < K && bn < N) {
                    size_t o = (size_t)bk * ldb + bn;
                    v1 = B1[o]; v2 = B2[o];
                }
                r1[q] = sub ? (v1 - v2) : v1;
                r2[q] = v2;
            }
        }
        const float* Ab  = As[buf];
        const float* B1b = B1s[buf];
        const float* B2b = B2s[buf];
        #pragma unroll
        for (int kk = 0; kk < 16; kk++) {
            float4 af = *(const float4*)&Ab[kk * 68 + (ty << 2)];
            ulonglong2 b1t = *(const ulonglong2*)&B1b[kk * 68 + (tx << 2)];
            ulonglong2 b2t = *(const ulonglong2*)&B2b[kk * 68 + (tx << 2)];
            float a[4] = {af.x, af.y, af.z, af.w};
            #pragma unroll
            for (int r = 0; r < 4; r++) {
                ull ap = pk2(a[r]);
                fma2(aU[r][0], ap, b1t.x);
                fma2(aU[r][1], ap, b1t.y);
                fma2(aV[r][0], ap, b2t.x);
                fma2(aV[r][1], ap, b2t.y);
            }
        }
        if (nk < K) {
            int nb = buf ^ 1;
            #pragma unroll
            for (int q = 0; q < 4; q++) {
                As[nb][(la_k + q) * 68 + la_m] = ra[q];
                B1s[nb][lb_k * 68 + lb_n + q] = r1[q];
                B2s[nb][lb_k * 68 + lb_n + q] = r2[q];
            }
            __syncthreads();
            buf = nb;
        }
    }

    #pragma unroll
    for (int r = 0; r < 4; r++) {
        int m = m0 + (ty << 2) + r;
        if (m >= M) continue;
        float u[4], v[4];
        unpk(aU[r][0], u[0], u[1]); unpk(aU[r][1], u[2], u[3]);
        unpk(aV[r][0], v[0], v[1]); unpk(aV[r][1], v[2], v[3]);
        #pragma unroll
        for (int c = 0; c < 4; c++) {
            int n = n0 + (tx << 2) + c;
            if (n >= N) continue;
            Uo[(size_t)m * ldu + n] = u[c];
            Vo[(size_t)m * ldu + n] = v[c];
        }
    }
}

// ---------------- fused global max pool + hg ----------------
__global__ void gmaxhg_kernel(const float* __restrict__ w1, const float* __restrict__ b1) {
    __shared__ float sg[128];
    int b = blockIdx.x, c = threadIdx.x;
    const float* p = g_sf + (size_t)b * NPTS * 128 + c;
    float m = -3.3e38f;
    #pragma unroll 4
    for (int n = 0; n < NPTS; n++) m = fmaxf(m, p[n * 128]);
    sg[c] = m;
    __syncthreads();
    float s = b1[c];
    #pragma unroll 4
    for (int d = 0; d < 128; d++) s += sg[d] * w1[(256 + d) * 128 + c];
    g_hg[b * 128 + c] = s;
}

// ---------------- pair kernel: 64x64 tile, 4x4 pairs/thread ----------------
__global__ void __launch_bounds__(256)
pair_kernel(const float* __restrict__ w2, const float* __restrict__ b2,
            float* __restrict__ out) {
    int bx = blockIdx.x, by = blockIdx.y;
    if (bx < by) return;
    int b = blockIdx.z;
    extern __shared__ float ps[];
    float* s_hi = ps;
    float* s_hj = ps + 64 * 132;
    float* s_w  = ps + 2 * 64 * 132;

    int tid = threadIdx.y * 16 + threadIdx.x;
    int bi0 = by * 64, bj0 = bx * 64;

    for (int t = tid; t < 64 * 32; t += 256) {
        int r = t >> 5, c4 = (t & 31) << 2;
        int gi = bi0 + r;
        float4 v = make_float4(0.f, 0.f, 0.f, 0.f);
        if (gi < NPTS) v = *(const float4*)&g_hi[((size_t)(b * NPTS + gi)) * 128 + c4];
        *(float4*)&s_hi[r * 132 + c4] = v;
        int gj = bj0 + r;
        float4 u = make_float4(0.f, 0.f, 0.f, 0.f);
        if (gj < NPTS) {
            u = *(const float4*)&g_hjg[((size_t)(b * NPTS + gj)) * 128 + c4];
            float4 hgv = *(const float4*)&g_hg[b * 128 + c4];
            u.x += hgv.x; u.y += hgv.y; u.z += hgv.z; u.w += hgv.w;
        }
        *(float4*)&s_hj[r * 132 + c4] = u;
    }
    if (tid < 32) *(float4*)&s_w[tid * 4] = *(const float4*)&w2[tid * 4];
    __syncthreads();

    int ri0 = threadIdx.y * 4, cj0 = threadIdx.x * 4;
    float acc[4][4] = {};
    for (int c4 = 0; c4 < 128; c4 += 4) {
        float4 w = *(const float4*)&s_w[c4];
        float4 A[4], H[4];
        #pragma unroll
        for (int r = 0; r < 4; r++) A[r] = *(const float4*)&s_hi[(ri0 + r) * 132 + c4];
        #pragma unroll
        for (int c = 0; c < 4; c++) H[c] = *(const float4*)&s_hj[(cj0 + c) * 132 + c4];
        #pragma unroll
        for (int r = 0; r < 4; r++)
            #pragma unroll
            for (int c = 0; c < 4; c++) {
                acc[r][c] += fmaxf(A[r].x + H[c].x, 0.f) * w.x
                           + fmaxf(A[r].y + H[c].y, 0.f) * w.y
                           + fmaxf(A[r].z + H[c].z, 0.f) * w.z
                           + fmaxf(A[r].w + H[c].w, 0.f) * w.w;
            }
    }

    float bias2 = b2[0];
    #pragma unroll
    for (int r = 0; r < 4; r++) {
        int gi = bi0 + ri0 + r;
        #pragma unroll
        for (int c = 0; c < 4; c++) {
            int gj = bj0 + cj0 + c;
            if (gj < NPTS && gi < gj) {
                float m = acc[r][c] + bias2;
                int p = gi * (NPTS - 1) - (gi * (gi - 1)) / 2 + (gj - gi - 1);
                int off = b * NPAIR + p;
                out[off] = 1.f / (1.f + __expf(-m));
                out[BATCH * NPAIR + off] = m;
            }
        }
    }
}

// ============================ host side ============================
static void* sym_addr(const void* s) {
    void* p = nullptr;
    cudaGetSymbolAddress(&p, s);
    return p;
}

static void gemm(const float* A, int lda, const float* B, int ldb,
                 float* C, int ldc, int M, int N, int K,
                 const float* bias, int dorelu) {
    dim3 g((M + 63) / 64, (N + 63) / 64);
    gemm_kernel<<<g, 256>>>(A, lda, B, ldb, C, ldc, M, N, K, bias, dorelu);
}

static void edge_conv(const float* x, int lda, int C, int H, int H2,
                      const float* w1, const float* b1,
                      const float* w2, const float* b2,
                      float* U, float* V, float* G,
                      float* outp, int ldo, float* outc) {
    xxt_kernel<<<dim3(8, 8, BATCH), 256>>>(x, lda, C, G);
    topk_kernel<<<BNODES / 8, 256>>>(G);
    dim3 guv((BNODES + 63) / 64, (H + 63) / 64);
    gemm_uv_kernel<<<guv, 256>>>(x, lda, w1, w1 + (size_t)C * H, H,
                                 U, V, H, BNODES, H, C, 1);
    fused_edge_gemm<<<dim3(125, (H2 + 127) / 128), 256>>>(U, V, b1, w2, b2,
                                                          outp, ldo, outc, H, H2);
}

extern "C" void kernel_launch(void* const* d_in, const int* in_sizes, int n_in,
                              void* d_out, int out_size) {
    const float* in[21];
    for (int i = 0; i < 21; i++) in[i] = (const float*)d_in[i];
    const float* pos   = in[0];
    const float* c1_w1 = in[1];  const float* c1_b1 = in[2];
    const float* c1_w2 = in[3];  const float* c1_b2 = in[4];
    const float* c2_w1 = in[5];  const float* c2_b1 = in[6];
    const float* c2_w2 = in[7];  const float* c2_b2 = in[8];
    const float* c3_w1 = in[9];  const float* c3_b1 = in[10];
    const float* c3_w2 = in[11]; const float* c3_b2 = in[12];
    const float* sm_w1 = in[13]; const float* sm_b1 = in[14];
    const float* sm_w2 = in[15]; const float* sm_b2 = in[16];
    const float* ec_w1 = in[17]; const float* ec_b1 = in[18];
    const float* ec_w2 = in[19]; const float* ec_b2 = in[20];

    float* x1  = (float*)sym_addr(g_x1);
    float* x2  = (float*)sym_addr(g_x2);
    float* U   = (float*)sym_addr(g_U);
    float* V   = (float*)sym_addr(g_V);
    float* G   = (float*)sym_addr(g_G);
    float* cat = (float*)sym_addr(g_cat);
    float* smh = (float*)sym_addr(g_smh);
    float* sf  = (float*)sym_addr(g_sf);
    float* hi  = (float*)sym_addr(g_hi);
    float* hjg = (float*)sym_addr(g_hjg);

    // conv1: pos[2000,3] -> x1 (32 ch) into cat+0 and compact g_x1
    edge_conv(pos, 3, 3, 16, 32, c1_w1, c1_b1, c1_w2, c1_b2, U, V, G, cat + 0, 672, x1);
    // conv2: g_x1 -> 128 ch into cat+32 and compact g_x2
    edge_conv(x1, 32, 32, 64, 128, c2_w1, c2_b1, c2_w2, c2_b2, U, V, G, cat + 32, 672, x2);
    // conv3: g_x2 -> 512 ch into cat+160
    edge_conv(x2, 128, 128, 256, 512, c3_w1, c3_b1, c3_w2, c3_b2, U, V, G, cat + 160, 672, nullptr);

    // sm MLP: [2000,672] -> relu 256 -> 128
    gemm(cat, 672, sm_w1, 256, smh, 256, BNODES, 256, 672, sm_b1, 1);
    gemm(smh, 256, sm_w2, 128, sf, 128, BNODES, 128, 256, sm_b2, 0);

    // fused global max pool + hg
    gmaxhg_kernel<<<BATCH, 128>>>(ec_w1, ec_b1);

    // hjg = sf @ ec_w1[128:256] ; hi = sf @ ec_w1[:128] (dual, no subtraction)
    dim3 ghh((BNODES + 63) / 64, 2);
    gemm_uv_kernel<<<ghh, 256>>>(sf, 128, ec_w1 + 128 * 128, ec_w1, 128,
                                 hjg, hi, 128, BNODES, 128, 128, 0);

    // fused pair stage -> d_out = [pair_prob (B*P), mlp_out (B*P)]
    size_t psmem = (2 * 64 * 132 + 128) * sizeof(float);
    cudaFuncSetAttribute(pair_kernel, cudaFuncAttributeMaxDynamicSharedMemorySize, (int)psmem);
    pair_kernel<<<dim3(16, 16, BATCH), dim3(16, 16), psmem>>>(ec_w2, ec_b2, (float*)d_out);
}

// round 7
// speedup vs baseline: 1.0592x; 1.0249x over previous
#include <cuda_runtime.h>
#include <math.h>

#define NPTS   1000
#define BATCH  2
#define BNODES 2000
#define KNN    8
#define NEDGE  (BNODES*KNN)
#define NPAIR  499500   // NPTS*(NPTS-1)/2

typedef unsigned long long ull;

// packed f32x2 helpers (Blackwell: fma.rn.f32x2 — PTX-only)
__device__ __forceinline__ ull pk2(float x) {
    ull r; asm("mov.b64 %0, {%1, %1};" : "=l"(r) : "f"(x)); return r;
}
__device__ __forceinline__ void fma2(ull& d, ull a, ull b) {
    asm("fma.rn.f32x2 %0, %1, %2, %0;" : "+l"(d) : "l"(a), "l"(b));
}
__device__ __forceinline__ void unpk(ull v, float& lo, float& hi) {
    asm("mov.b64 {%0, %1}, %2;" : "=f"(lo), "=f"(hi) : "l"(v));
}

// ---------------- scratch (static __device__; no allocations) ----------------
__device__ float g_sq[BNODES];
__device__ int   g_idx[NEDGE];
__device__ __align__(16) float g_x1[BNODES*32];
__device__ __align__(16) float g_x2[BNODES*128];
__device__ __align__(16) float g_U[BNODES*256];
__device__ __align__(16) float g_V[BNODES*256];
__device__ __align__(16) float g_G[BATCH*NPTS*NPTS];
__device__ __align__(16) float g_cat[BNODES*672];
__device__ __align__(16) float g_smh[BNODES*256];
__device__ __align__(16) float g_sf[BNODES*128];
__device__ __align__(16) float g_hi[BNODES*128];
__device__ __align__(16) float g_hjg[BNODES*128];
__device__ __align__(16) float g_hg[BATCH*128];

// -------- X @ X^T, symmetric: 36 upper tiles per batch, mirror store ------------------
__global__ void __launch_bounds__(256, 2)
xxt_kernel(const float* __restrict__ x, int lda, int C, float* __restrict__ G) {
    __shared__ __align__(16) float As[2][16 * 132];
    __shared__ __align__(16) float Bs[2][16 * 132];
    int b = blockIdx.y;
    // decode upper-triangular tile (ti <= tj) from blockIdx.x in [0,36)
    int t = blockIdx.x, ti = 0;
    while (t >= 8 - ti) { t -= 8 - ti; ti++; }
    int tj = ti + t;
    int m0 = ti * 128, n0 = tj * 128;
    const float* xb = x + (size_t)b * NPTS * lda;
    int tid  = threadIdx.x;
    int lrow = tid >> 1, lk8 = (tid & 1) * 8;
    int tx = tid & 15, ty = tid >> 4;
    ull acc2[8][4];
    #pragma unroll
    for (int r = 0; r < 8; r++)
        #pragma unroll
        for (int q = 0; q < 4; q++) acc2[r][q] = 0ull;

    int ar = m0 + lrow, br = n0 + lrow;
    float ra[8], rb[8];
    #pragma unroll
    for (int q = 0; q < 8; q++) {
        int k = lk8 + q;
        ra[q] = (ar < NPTS && k < C) ? xb[(size_t)ar * lda + k] : 0.f;
        rb[q] = (br < NPTS && k < C) ? xb[(size_t)br * lda + k] : 0.f;
    }
    #pragma unroll
    for (int q = 0; q < 8; q++) {
        As[0][(lk8 + q) * 132 + lrow] = ra[q];
        Bs[0][(lk8 + q) * 132 + lrow] = rb[q];
    }
    __syncthreads();

    int buf = 0;
    for (int k0 = 0; k0 < C; k0 += 16) {
        int nk = k0 + 16;
        if (nk < C) {
            #pragma unroll
            for (int q = 0; q < 8; q++) {
                int k = nk + lk8 + q;
                ra[q] = (ar < NPTS && k < C) ? xb[(size_t)ar * lda + k] : 0.f;
                rb[q] = (br < NPTS && k < C) ? xb[(size_t)br * lda + k] : 0.f;
            }
        }
        const float* Ab = As[buf];
        const float* Bb = Bs[buf];
        #pragma unroll
        for (int kk = 0; kk < 16; kk++) {
            float a[8];
            *(float4*)&a[0] = *(const float4*)&Ab[kk * 132 + ty * 8];
            *(float4*)&a[4] = *(const float4*)&Ab[kk * 132 + ty * 8 + 4];
            ull bp[4];
            {
                ulonglong2 t0 = *(const ulonglong2*)&Bb[kk * 132 + tx * 8];
                ulonglong2 t1 = *(const ulonglong2*)&Bb[kk * 132 + tx * 8 + 4];
                bp[0] = t0.x; bp[1] = t0.y; bp[2] = t1.x; bp[3] = t1.y;
            }
            #pragma unroll
            for (int r = 0; r < 8; r++) {
                ull ap = pk2(a[r]);
                #pragma unroll
                for (int q = 0; q < 4; q++) fma2(acc2[r][q], ap, bp[q]);
            }
        }
        if (nk < C) {
            int nb = buf ^ 1;
            #pragma unroll
            for (int q = 0; q < 8; q++) {
                As[nb][(lk8 + q) * 132 + lrow] = ra[q];
                Bs[nb][(lk8 + q) * 132 + lrow] = rb[q];
            }
            __syncthreads();
            buf = nb;
        }
    }
    float* Gb = G + (size_t)b * NPTS * NPTS;
    #pragma unroll
    for (int r = 0; r < 8; r++) {
        int i = m0 + ty * 8 + r;
        if (i >= NPTS) continue;
        #pragma unroll
        for (int q = 0; q < 4; q++) {
            float lo, hi;
            unpk(acc2[r][q], lo, hi);
            int j0 = n0 + tx * 8 + 2 * q;
            int j1 = j0 + 1;
            if (j0 < NPTS) {
                Gb[(size_t)i * NPTS + j0] = lo;
                if (ti != tj) Gb[(size_t)j0 * NPTS + i] = lo;
                else if (i == j0) g_sq[b * NPTS + i] = lo;
            }
            if (j1 < NPTS) {
                Gb[(size_t)i * NPTS + j1] = hi;
                if (ti != tj) Gb[(size_t)j1 * NPTS + i] = hi;
                else if (i == j1) g_sq[b * NPTS + i] = hi;
            }
        }
    }
}

// ---------------- warp-parallel top-8 (ties -> lowest idx), 8 nodes/block --------------
__global__ void __launch_bounds__(256)
topk_kernel(const float* __restrict__ G) {
    int warp = threadIdx.x >> 5, lane = threadIdx.x & 31;
    int node = blockIdx.x * 8 + warp;
    int b = node / NPTS, i = node - b * NPTS, base = b * NPTS;
    const float* Grow = G + ((size_t)b * NPTS + i) * NPTS;
    float sqi = g_sq[node];

    float val[8]; int idx[8];
    #pragma unroll
    for (int q = 0; q < 8; q++) { val[q] = 3.3e38f; idx[q] = 0x7FFFFFFF; }

    for (int j = lane; j < NPTS; j += 32) {
        float v = sqi + g_sq[base + j] - 2.f * Grow[j];
        bool lt = (v < val[7]) || (v == val[7] && j < idx[7]);
        if (lt) {
            val[7] = v; idx[7] = j;
            #pragma unroll
            for (int q = 7; q > 0; q--) {
                bool sw = (val[q] < val[q - 1]) ||
                          (val[q] == val[q - 1] && idx[q] < idx[q - 1]);
                if (sw) {
                    float tv = val[q]; val[q] = val[q - 1]; val[q - 1] = tv;
                    int ti = idx[q]; idx[q] = idx[q - 1]; idx[q - 1] = ti;
                }
            }
        }
    }

    #pragma unroll
    for (int kk = 0; kk < KNN; kk++) {
        float bv = val[0]; int bi = idx[0];
        #pragma unroll
        for (int o = 16; o; o >>= 1) {
            float ov = __shfl_xor_sync(0xFFFFFFFFu, bv, o);
            int   oi = __shfl_xor_sync(0xFFFFFFFFu, bi, o);
            if (ov < bv || (ov == bv && oi < bi)) { bv = ov; bi = oi; }
        }
        if (lane == 0) g_idx[node * KNN + kk] = base + bi;
        if (idx[0] == bi && val[0] == bv) {
            #pragma unroll
            for (int q = 0; q < 7; q++) { val[q] = val[q + 1]; idx[q] = idx[q + 1]; }
            val[7] = 3.3e38f; idx[7] = 0x7FFFFFFF;
        }
    }
}

// -------- fused edge GEMM: A=relu(U[i]+V[j]+b1) on the fly, double-buffered ------------
__global__ void __launch_bounds__(256, 2)
fused_edge_gemm(const float* __restrict__ U, const float* __restrict__ V,
                const float* __restrict__ b1, const float* __restrict__ W2,
                const float* __restrict__ b2, float* __restrict__ out,
                int ldo, float* __restrict__ outc, int H, int H2) {
    __shared__ __align__(16) float As[2][16 * 132];
    __shared__ __align__(16) float Bs[2][16 * 132];
    __shared__ float sb1[256];
    int tid = threadIdx.x;
    int m0 = blockIdx.x * 128, n0 = blockIdx.y * 128;
    int tx = tid & 15, ty = tid >> 4;
    if (tid < H) sb1[tid] = b1[tid];
    ull acc2[8][4];
    #pragma unroll
    for (int r = 0; r < 8; r++)
        #pragma unroll
        for (int q = 0; q < 4; q++) acc2[r][q] = 0ull;

    int arow = tid >> 1, ak8 = (tid & 1) * 8;
    int e = m0 + arow;
    const float* Urow = U + (size_t)(e >> 3) * H;
    const float* Vrow = V + (size_t)g_idx[e] * H;
    int bk = tid >> 4, bn8 = (tid & 15) * 8;

    float ru[8], rv[8], rb[8];
    {
        float4 u0 = *(const float4*)&Urow[ak8];
        float4 u1 = *(const float4*)&Urow[ak8 + 4];
        float4 v0 = *(const float4*)&Vrow[ak8];
        float4 v1 = *(const float4*)&Vrow[ak8 + 4];
        ru[0] = u0.x; ru[1] = u0.y; ru[2] = u0.z; ru[3] = u0.w;
        ru[4] = u1.x; ru[5] = u1.y; ru[6] = u1.z; ru[7] = u1.w;
        rv[0] = v0.x; rv[1] = v0.y; rv[2] = v0.z; rv[3] = v0.w;
        rv[4] = v1.x; rv[5] = v1.y; rv[6] = v1.z; rv[7] = v1.w;
        if (n0 + bn8 + 7 < H2) {
            float4 w0 = *(const float4*)&W2[(size_t)bk * H2 + n0 + bn8];
            float4 w1 = *(const float4*)&W2[(size_t)bk * H2 + n0 + bn8 + 4];
            rb[0] = w0.x; rb[1] = w0.y; rb[2] = w0.z; rb[3] = w0.w;
            rb[4] = w1.x; rb[5] = w1.y; rb[6] = w1.z; rb[7] = w1.w;
        } else {
            #pragma unroll
            for (int q = 0; q < 8; q++) {
                int n = n0 + bn8 + q;
                rb[q] = (n < H2) ? W2[(size_t)bk * H2 + n] : 0.f;
            }
        }
    }
    __syncthreads();
    #pragma unroll
    for (int q = 0; q < 8; q++) {
        As[0][(ak8 + q) * 132 + arow] = fmaxf(ru[q] + rv[q] + sb1[ak8 + q], 0.f);
        Bs[0][bk * 132 + bn8 + q] = rb[q];
    }
    __syncthreads();

    int buf = 0;
    for (int k0 = 0; k0 < H; k0 += 16) {
        int nk = k0 + 16;
        if (nk < H) {
            float4 u0 = *(const float4*)&Urow[nk + ak8];
            float4 u1 = *(const float4*)&Urow[nk + ak8 + 4];
            float4 v0 = *(const float4*)&Vrow[nk + ak8];
            float4 v1 = *(const float4*)&Vrow[nk + ak8 + 4];
            ru[0] = u0.x; ru[1] = u0.y; ru[2] = u0.z; ru[3] = u0.w;
            ru[4] = u1.x; ru[5] = u1.y; ru[6] = u1.z; ru[7] = u1.w;
            rv[0] = v0.x; rv[1] = v0.y; rv[2] = v0.z; rv[3] = v0.w;
            rv[4] = v1.x; rv[5] = v1.y; rv[6] = v1.z; rv[7] = v1.w;
            if (n0 + bn8 + 7 < H2) {
                float4 w0 = *(const float4*)&W2[(size_t)(nk + bk) * H2 + n0 + bn8];
                float4 w1 = *(const float4*)&W2[(size_t)(nk + bk) * H2 + n0 + bn8 + 4];
                rb[0] = w0.x; rb[1] = w0.y; rb[2] = w0.z; rb[3] = w0.w;
                rb[4] = w1.x; rb[5] = w1.y; rb[6] = w1.z; rb[7] = w1.w;
            } else {
                #pragma unroll
                for (int q = 0; q < 8; q++) {
                    int n = n0 + bn8 + q;
                    rb[q] = (n < H2) ? W2[(size_t)(nk + bk) * H2 + n] : 0.f;
                }
            }
        }
        const float* Ab = As[buf];
        const float* Bb = Bs[buf];
        #pragma unroll
        for (int kk = 0; kk < 16; kk++) {
            float a[8];
            *(float4*)&a[0] = *(const float4*)&Ab[kk * 132 + ty * 8];
            *(float4*)&a[4] = *(const float4*)&Ab[kk * 132 + ty * 8 + 4];
            ull bp[4];
            {
                ulonglong2 t0 = *(const ulonglong2*)&Bb[kk * 132 + tx * 8];
                ulonglong2 t1 = *(const ulonglong2*)&Bb[kk * 132 + tx * 8 + 4];
                bp[0] = t0.x; bp[1] = t0.y; bp[2] = t1.x; bp[3] = t1.y;
            }
            #pragma unroll
            for (int r = 0; r < 8; r++) {
                ull ap = pk2(a[r]);
                #pragma unroll
                for (int q = 0; q < 4; q++) fma2(acc2[r][q], ap, bp[q]);
            }
        }
        if (nk < H) {
            int nb = buf ^ 1;
            #pragma unroll
            for (int q = 0; q < 8; q++) {
                As[nb][(ak8 + q) * 132 + arow] = fmaxf(ru[q] + rv[q] + sb1[nk + ak8 + q], 0.f);
                Bs[nb][bk * 132 + bn8 + q] = rb[q];
            }
            __syncthreads();
            buf = nb;
        }
    }

    // epilogue: rows ty*8..ty*8+7 are the 8 edges of one node; stream per column-pair
    int node = (m0 >> 3) + ty;
    #pragma unroll
    for (int q = 0; q < 4; q++) {
        int nA = n0 + tx * 8 + 2 * q;
        int nB = nA + 1;
        float mA = -3.3e38f, mB = -3.3e38f;
        #pragma unroll
        for (int r = 0; r < 8; r++) {
            float lo, hi;
            unpk(acc2[r][q], lo, hi);
            mA = fmaxf(mA, lo);
            mB = fmaxf(mB, hi);
        }
        if (nA < H2) {
            float v = mA + b2[nA];
            out[(size_t)node * ldo + nA] = v;
            if (outc) outc[(size_t)node * H2 + nA] = v;
        }
        if (nB < H2) {
            float v = mB + b2[nB];
            out[(size_t)node * ldo + nB] = v;
            if (outc) outc[(size_t)node * H2 + nB] = v;
        }
    }
}

// ------------- generic fp32 GEMM (64x64, 4x4, f32x2, double-buffered) ------------------
__global__ void __launch_bounds__(256, 2)
gemm_kernel(const float* __restrict__ A, int lda,
            const float* __restrict__ B, int ldb,
            float* __restrict__ C, int ldc,
            int M, int N, int K,
            const float* __restrict__ bias, int dorelu) {
    __shared__ __align__(16) float As[2][16 * 68];
    __shared__ __align__(16) float Bs[2][16 * 68];
    int tid = threadIdx.x;
    int tx = tid & 15, ty = tid >> 4;
    int m0 = blockIdx.x * 64, n0 = blockIdx.y * 64;
    ull acc2[4][2];
    #pragma unroll
    for (int r = 0; r < 4; r++) { acc2[r][0] = 0ull; acc2[r][1] = 0ull; }

    int la_m = tid >> 2;
    int la_k = (tid & 3) << 2;
    int lb_k = tid >> 4;
    int lb_n = (tid & 15) << 2;
    int am = m0 + la_m;

    float ra[4], rbv[4];
    #pragma unroll
    for (int q = 0; q < 4; q++) {
        int ak = la_k + q;
        ra[q] = (am < M && ak < K) ? A[(size_t)am * lda + ak] : 0.f;
        int bn = n0 + lb_n + q;
        rbv[q] = (lb_k < K && bn < N) ? B[(size_t)lb_k * ldb + bn] : 0.f;
    }
    #pragma unroll
    for (int q = 0; q < 4; q++) {
        As[0][(la_k + q) * 68 + la_m] = ra[q];
        Bs[0][lb_k * 68 + lb_n + q] = rbv[q];
    }
    __syncthreads();

    int buf = 0;
    for (int k0 = 0; k0 < K; k0 += 16) {
        int nk = k0 + 16;
        if (nk < K) {
            #pragma unroll
            for (int q = 0; q < 4; q++) {
                int ak = nk + la_k + q;
                ra[q] = (am < M && ak < K) ? A[(size_t)am * lda + ak] : 0.f;
                int bn = n0 + lb_n + q;
                int bk = nk + lb_k;
                rbv[q] = (bk < K && bn < N) ? B[(size_t)bk * ldb + bn] : 0.f;
            }
        }
        const float* Ab = As[buf];
        const float* Bb = Bs[buf];
        #pragma unroll
        for (int kk = 0; kk < 16; kk++) {
            float4 af = *(const float4*)&Ab[kk * 68 + (ty << 2)];
            ulonglong2 bt = *(const ulonglong2*)&Bb[kk * 68 + (tx << 2)];
            float a[4] = {af.x, af.y, af.z, af.w};
            #pragma unroll
            for (int r = 0; r < 4; r++) {
                ull ap = pk2(a[r]);
                fma2(acc2[r][0], ap, bt.x);
                fma2(acc2[r][1], ap, bt.y);
            }
        }
        if (nk < K) {
            int nb = buf ^ 1;
            #pragma unroll
            for (int q = 0; q < 4; q++) {
                As[nb][(la_k + q) * 68 + la_m] = ra[q];
                Bs[nb][lb_k * 68 + lb_n + q] = rbv[q];
            }
            __syncthreads();
            buf = nb;
        }
    }

    #pragma unroll
    for (int r = 0; r < 4; r++) {
        int m = m0 + (ty << 2) + r;
        if (m >= M) continue;
        float av[4];
        unpk(acc2[r][0], av[0], av[1]);
        unpk(acc2[r][1], av[2], av[3]);
        #pragma unroll
        for (int c = 0; c < 4; c++) {
            int n = n0 + (tx << 2) + c;
            if (n >= N) continue;
            float v = av[c];
            if (bias) v += bias[n];
            if (dorelu) v = fmaxf(v, 0.f);
            C[(size_t)m * ldc + n] = v;
        }
    }
}

// ------------- dual GEMM (double-buffered): Uo = A@(B1 - sub*B2), Vo = A@B2 ------------
__global__ void __launch_bounds__(256, 2)
gemm_uv_kernel(const float* __restrict__ A, int lda,
               const float* __restrict__ B1, const float* __restrict__ B2, int ldb,
               float* __restrict__ Uo, float* __restrict__ Vo, int ldu,
               int M, int N, int K, int sub) {
    __shared__ __align__(16) float As[2][16 * 68];
    __shared__ __align__(16) float B1s[2][16 * 68];
    __shared__ __align__(16) float B2s[2][16 * 68];
    int tid = threadIdx.x;
    int tx = tid & 15, ty = tid >> 4;
    int m0 = blockIdx.x * 64, n0 = blockIdx.y * 64;
    ull aU[4][2], aV[4][2];
    #pragma unroll
    for (int r = 0; r < 4; r++) {
        aU[r][0] = aU[r][1] = 0ull;
        aV[r][0] = aV[r][1] = 0ull;
    }
    int la_m = tid >> 2;
    int la_k = (tid & 3) << 2;
    int lb_k = tid >> 4;
    int lb_n = (tid & 15) << 2;
    int am = m0 + la_m;

    float ra[4], r1[4], r2[4];
    #pragma unroll
    for (int q = 0; q < 4; q++) {
        int ak = la_k + q;
        ra[q] = (am < M && ak < K) ? A[(size_t)am * lda + ak] : 0.f;
        int bn = n0 + lb_n + q;
        float v1 = 0.f, v2 = 0.f;
        if (lb_k < K && bn < N) {
            size_t o = (size_t)lb_k * ldb + bn;
            v1 = B1[o]; v2 = B2[o];
        }
        r1[q] = sub ? (v1 - v2) : v1;
        r2[q] = v2;
    }
    #pragma unroll
    for (int q = 0; q < 4; q++) {
        As[0][(la_k + q) * 68 + la_m] = ra[q];
        B1s[0][lb_k * 68 + lb_n + q] = r1[q];
        B2s[0][lb_k * 68 + lb_n + q] = r2[q];
    }
    __syncthreads();

    int buf = 0;
    for (int k0 = 0; k0 < K; k0 += 16) {
        int nk = k0 + 16;
        if (nk < K) {
            #pragma unroll
            for (int q = 0; q < 4; q++) {
                int ak = nk + la_k + q;
                ra[q] = (am < M && ak < K) ? A[(size_t)am * lda + ak] : 0.f;
                int bn = n0 + lb_n + q;
                int bk = nk + lb_k;
                float v1 = 0.f, v2 = 0.f;
                if (bk < K && bn < N) {
                    size_t o = (size_t)bk * ldb + bn;
                    v1 = B1[o]; v2 = B2[o];
                }
                r1[q] = sub ? (v1 - v2) : v1;
                r2[q] = v2;
            }
        }
        const float* Ab  = As[buf];
        const float* B1b = B1s[buf];
        const float* B2b = B2s[buf];
        #pragma unroll
        for (int kk = 0; kk < 16; kk++) {
            float4 af = *(const float4*)&Ab[kk * 68 + (ty << 2)];
            ulonglong2 b1t = *(const ulonglong2*)&B1b[kk * 68 + (tx << 2)];
            ulonglong2 b2t = *(const ulonglong2*)&B2b[kk * 68 + (tx << 2)];
            float a[4] = {af.x, af.y, af.z, af.w};
            #pragma unroll
            for (int r = 0; r < 4; r++) {
                ull ap = pk2(a[r]);
                fma2(aU[r][0], ap, b1t.x);
                fma2(aU[r][1], ap, b1t.y);
                fma2(aV[r][0], ap, b2t.x);
                fma2(aV[r][1], ap, b2t.y);
            }
        }
        if (nk < K) {
            int nb = buf ^ 1;
            #pragma unroll
            for (int q = 0; q < 4; q++) {
                As[nb][(la_k + q) * 68 + la_m] = ra[q];
                B1s[nb][lb_k * 68 + lb_n + q] = r1[q];
                B2s[nb][lb_k * 68 + lb_n + q] = r2[q];
            }
            __syncthreads();
            buf = nb;
        }
    }

    #pragma unroll
    for (int r = 0; r < 4; r++) {
        int m = m0 + (ty << 2) + r;
        if (m >= M) continue;
        float u[4], v[4];
        unpk(aU[r][0], u[0], u[1]); unpk(aU[r][1], u[2], u[3]);
        unpk(aV[r][0], v[0], v[1]); unpk(aV[r][1], v[2], v[3]);
        #pragma unroll
        for (int c = 0; c < 4; c++) {
            int n = n0 + (tx << 2) + c;
            if (n >= N) continue;
            Uo[(size_t)m * ldu + n] = u[c];
            Vo[(size_t)m * ldu + n] = v[c];
        }
    }
}

// ---------------- fused global max pool + hg ----------------
__global__ void gmaxhg_kernel(const float* __restrict__ w1, const float* __restrict__ b1) {
    __shared__ float sg[128];
    int b = blockIdx.x, c = threadIdx.x;
    const float* p = g_sf + (size_t)b * NPTS * 128 + c;
    float m = -3.3e38f;
    #pragma unroll 4
    for (int n = 0; n < NPTS; n++) m = fmaxf(m, p[n * 128]);
    sg[c] = m;
    __syncthreads();
    float s = b1[c];
    #pragma unroll 4
    for (int d = 0; d < 128; d++) s += sg[d] * w1[(256 + d) * 128 + c];
    g_hg[b * 128 + c] = s;
}

// ---------------- pair kernel: 64x64 tile, 4x4 pairs/thread ----------------
__global__ void __launch_bounds__(256)
pair_kernel(const float* __restrict__ w2, const float* __restrict__ b2,
            float* __restrict__ out) {
    int bx = blockIdx.x, by = blockIdx.y;
    if (bx < by) return;
    int b = blockIdx.z;
    extern __shared__ float ps[];
    float* s_hi = ps;
    float* s_hj = ps + 64 * 132;
    float* s_w  = ps + 2 * 64 * 132;

    int tid = threadIdx.y * 16 + threadIdx.x;
    int bi0 = by * 64, bj0 = bx * 64;

    for (int t = tid; t < 64 * 32; t += 256) {
        int r = t >> 5, c4 = (t & 31) << 2;
        int gi = bi0 + r;
        float4 v = make_float4(0.f, 0.f, 0.f, 0.f);
        if (gi < NPTS) v = *(const float4*)&g_hi[((size_t)(b * NPTS + gi)) * 128 + c4];
        *(float4*)&s_hi[r * 132 + c4] = v;
        int gj = bj0 + r;
        float4 u = make_float4(0.f, 0.f, 0.f, 0.f);
        if (gj < NPTS) {
            u = *(const float4*)&g_hjg[((size_t)(b * NPTS + gj)) * 128 + c4];
            float4 hgv = *(const float4*)&g_hg[b * 128 + c4];
            u.x += hgv.x; u.y += hgv.y; u.z += hgv.z; u.w += hgv.w;
        }
        *(float4*)&s_hj[r * 132 + c4] = u;
    }
    if (tid < 32) *(float4*)&s_w[tid * 4] = *(const float4*)&w2[tid * 4];
    __syncthreads();

    int ri0 = threadIdx.y * 4, cj0 = threadIdx.x * 4;
    float acc[4][4] = {};
    for (int c4 = 0; c4 < 128; c4 += 4) {
        float4 w = *(const float4*)&s_w[c4];
        float4 A[4], H[4];
        #pragma unroll
        for (int r = 0; r < 4; r++) A[r] = *(const float4*)&s_hi[(ri0 + r) * 132 + c4];
        #pragma unroll
        for (int c = 0; c < 4; c++) H[c] = *(const float4*)&s_hj[(cj0 + c) * 132 + c4];
        #pragma unroll
        for (int r = 0; r < 4; r++)
            #pragma unroll
            for (int c = 0; c < 4; c++) {
                acc[r][c] += fmaxf(A[r].x + H[c].x, 0.f) * w.x
                           + fmaxf(A[r].y + H[c].y, 0.f) * w.y
                           + fmaxf(A[r].z + H[c].z, 0.f) * w.z
                           + fmaxf(A[r].w + H[c].w, 0.f) * w.w;
            }
    }

    float bias2 = b2[0];
    #pragma unroll
    for (int r = 0; r < 4; r++) {
        int gi = bi0 + ri0 + r;
        #pragma unroll
        for (int c = 0; c < 4; c++) {
            int gj = bj0 + cj0 + c;
            if (gj < NPTS && gi < gj) {
                float m = acc[r][c] + bias2;
                int p = gi * (NPTS - 1) - (gi * (gi - 1)) / 2 + (gj - gi - 1);
                int off = b * NPAIR + p;
                out[off] = 1.f / (1.f + __expf(-m));
                out[BATCH * NPAIR + off] = m;
            }
        }
    }
}

// ============================ host side ============================
static void* sym_addr(const void* s) {
    void* p = nullptr;
    cudaGetSymbolAddress(&p, s);
    return p;
}

extern "C" void kernel_launch(void* const* d_in, const int* in_sizes, int n_in,
                              void* d_out, int out_size) {
    const float* in[21];
    for (int i = 0; i < 21; i++) in[i] = (const float*)d_in[i];
    const float* pos   = in[0];
    const float* c1_w1 = in[1];  const float* c1_b1 = in[2];
    const float* c1_w2 = in[3];  const float* c1_b2 = in[4];
    const float* c2_w1 = in[5];  const float* c2_b1 = in[6];
    const float* c2_w2 = in[7];  const float* c2_b2 = in[8];
    const float* c3_w1 = in[9];  const float* c3_b1 = in[10];
    const float* c3_w2 = in[11]; const float* c3_b2 = in[12];
    const float* sm_w1 = in[13]; const float* sm_b1 = in[14];
    const float* sm_w2 = in[15]; const float* sm_b2 = in[16];
    const float* ec_w1 = in[17]; const float* ec_b1 = in[18];
    const float* ec_w2 = in[19]; const float* ec_b2 = in[20];

    float* x1  = (float*)sym_addr(g_x1);
    float* x2  = (float*)sym_addr(g_x2);
    float* U   = (float*)sym_addr(g_U);
    float* V   = (float*)sym_addr(g_V);
    float* G   = (float*)sym_addr(g_G);
    float* cat = (float*)sym_addr(g_cat);
    float* smh = (float*)sym_addr(g_smh);
    float* sf  = (float*)sym_addr(g_sf);
    float* hi  = (float*)sym_addr(g_hi);
    float* hjg = (float*)sym_addr(g_hjg);

    // side stream + events for fork/join inside graph capture.
    // Host code only runs during correctness + capture (graph replay skips it),
    // so per-call creation cost is irrelevant; not destroyed (few calls total).
    cudaStream_t s1;
    cudaStreamCreateWithFlags(&s1, cudaStreamNonBlocking);
    cudaEvent_t ev[10];
    for (int i = 0; i < 10; i++) cudaEventCreateWithFlags(&ev[i], cudaEventDisableTiming);
    int ei = 0;

    struct LayerP {
        const float* x; int lda, C, H, H2;
        const float* w1; const float* b1; const float* w2; const float* b2;
        float* outp; int ldo; float* outc;
    } L[3] = {
        { pos, 3,   3,   16,  32,  c1_w1, c1_b1, c1_w2, c1_b2, cat + 0,   672, x1 },
        { x1,  32,  32,  64,  128, c2_w1, c2_b1, c2_w2, c2_b2, cat + 32,  672, x2 },
        { x2,  128, 128, 256, 512, c3_w1, c3_b1, c3_w2, c3_b2, cat + 160, 672, nullptr },
    };

    for (int l = 0; l < 3; l++) {
        // fork: uv on s1, xxt+topk on main
        cudaEventRecord(ev[ei], 0);
        cudaStreamWaitEvent(s1, ev[ei], 0); ei++;
        dim3 guv((BNODES + 63) / 64, (L[l].H + 63) / 64);
        gemm_uv_kernel<<<guv, 256, 0, s1>>>(L[l].x, L[l].lda, L[l].w1,
                                            L[l].w1 + (size_t)L[l].C * L[l].H, L[l].H,
                                            U, V, L[l].H, BNODES, L[l].H, L[l].C, 1);
        cudaEventRecord(ev[ei], s1);

        xxt_kernel<<<dim3(36, BATCH), 256>>>(L[l].x, L[l].lda, L[l].C, G);
        topk_kernel<<<BNODES / 8, 256>>>(G);

        cudaStreamWaitEvent(0, ev[ei], 0); ei++;   // join uv
        fused_edge_gemm<<<dim3(125, (L[l].H2 + 127) / 128), 256>>>(
            U, V, L[l].b1, L[l].w2, L[l].b2, L[l].outp, L[l].ldo, L[l].outc,
            L[l].H, L[l].H2);
    }

    // sm MLP: [2000,672] -> relu 256 -> 128
    {
        dim3 g1((BNODES + 63) / 64, 4);
        gemm_kernel<<<g1, 256>>>(cat, 672, sm_w1, 256, smh, 256, BNODES, 256, 672, sm_b1, 1);
        dim3 g2((BNODES + 63) / 64, 2);
        gemm_kernel<<<g2, 256>>>(smh, 256, sm_w2, 128, sf, 128, BNODES, 128, 256, sm_b2, 0);
    }

    // fork: hi/hjg dual GEMM on s1, gmax+hg on main
    cudaEventRecord(ev[ei], 0);
    cudaStreamWaitEvent(s1, ev[ei], 0); ei++;
    dim3 ghh((BNODES + 63) / 64, 2);
    gemm_uv_kernel<<<ghh, 256, 0, s1>>>(sf, 128, ec_w1 + 128 * 128, ec_w1, 128,
                                        hjg, hi, 128, BNODES, 128, 128, 0);
    cudaEventRecord(ev[ei], s1);

    gmaxhg_kernel<<<BATCH, 128>>>(ec_w1, ec_b1);

    cudaStreamWaitEvent(0, ev[ei], 0); ei++;       // join

    // fused pair stage -> d_out = [pair_prob (B*P), mlp_out (B*P)]
    size_t psmem = (2 * 64 * 132 + 128) * sizeof(float);
    cudaFuncSetAttribute(pair_kernel, cudaFuncAttributeMaxDynamicSharedMemorySize, (int)psmem);
    pair_kernel<<<dim3(16, 16, BATCH), dim3(16, 16), psmem>>>(ec_w2, ec_b2, (float*)d_out);
}

// round 8
// speedup vs baseline: 1.2384x; 1.1693x over previous
#include <cuda_runtime.h>
#include <cuda_bf16.h>
#include <math.h>

#define NPTS   1000
#define BATCH  2
#define BNODES 2000
#define KNN    8
#define NEDGE  (BNODES*KNN)
#define NPAIR  499500   // NPTS*(NPTS-1)/2

typedef unsigned long long ull;
typedef unsigned int uint;

// packed f32x2 helpers (Blackwell: fma.rn.f32x2 — PTX-only)
__device__ __forceinline__ ull pk2(float x) {
    ull r; asm("mov.b64 %0, {%1, %1};" : "=l"(r) : "f"(x)); return r;
}
__device__ __forceinline__ void fma2(ull& d, ull a, ull b) {
    asm("fma.rn.f32x2 %0, %1, %2, %0;" : "+l"(d) : "l"(a), "l"(b));
}
__device__ __forceinline__ void unpk(ull v, float& lo, float& hi) {
    asm("mov.b64 {%0, %1}, %2;" : "=f"(lo), "=f"(hi) : "l"(v));
}

// bf16 split helpers
__device__ __forceinline__ uint bfpack2(__nv_bfloat16 lo, __nv_bfloat16 hi) {
    return ((uint)__bfloat16_as_ushort(hi) << 16) | (uint)__bfloat16_as_ushort(lo);
}
// split f0,f1 (consecutive k) into hi-pair and lo-pair packed words
__device__ __forceinline__ void bsplit2(float f0, float f1, uint& hp, uint& lp) {
    __nv_bfloat16 h0 = __float2bfloat16_rn(f0);
    __nv_bfloat16 h1 = __float2bfloat16_rn(f1);
    float l0 = f0 - __bfloat162float(h0);
    float l1 = f1 - __bfloat162float(h1);
    hp = bfpack2(h0, h1);
    lp = bfpack2(__float2bfloat16_rn(l0), __float2bfloat16_rn(l1));
}

#define MMA_BF16(c, a0, a1, a2, a3, b0, b1)                                     \
    asm volatile("mma.sync.aligned.m16n8k16.row.col.f32.bf16.bf16.f32 "          \
                 "{%0,%1,%2,%3}, {%4,%5,%6,%7}, {%8,%9}, {%0,%1,%2,%3};"         \
                 : "+f"((c)[0]), "+f"((c)[1]), "+f"((c)[2]), "+f"((c)[3])        \
                 : "r"(a0), "r"(a1), "r"(a2), "r"(a3), "r"(b0), "r"(b1))

// ---------------- scratch (static __device__; no allocations) ----------------
__device__ float g_sq[BNODES];
__device__ int   g_idx[NEDGE];
__device__ __align__(16) float g_x1[BNODES*32];
__device__ __align__(16) float g_x2[BNODES*128];
__device__ __align__(16) float g_U[BNODES*256];
__device__ __align__(16) float g_V[BNODES*256];
__device__ __align__(16) float g_G[BATCH*NPTS*NPTS];
__device__ __align__(16) float g_cat[BNODES*672];
__device__ __align__(16) float g_smh[BNODES*256];
__device__ __align__(16) float g_sf[BNODES*128];
__device__ __align__(16) float g_hi[BNODES*128];
__device__ __align__(16) float g_hjg[BNODES*128];
__device__ __align__(16) float g_hg[BATCH*128];
__device__ __align__(16) float g_pmax[BATCH*25*128];

// -------- X @ X^T, symmetric: 36 upper tiles per batch, mirror store ------------------
__global__ void __launch_bounds__(256, 2)
xxt_kernel(const float* __restrict__ x, int lda, int C, float* __restrict__ G) {
    __shared__ __align__(16) float As[2][16 * 132];
    __shared__ __align__(16) float Bs[2][16 * 132];
    int b = blockIdx.y;
    int t = blockIdx.x, ti = 0;
    while (t >= 8 - ti) { t -= 8 - ti; ti++; }
    int tj = ti + t;
    int m0 = ti * 128, n0 = tj * 128;
    const float* xb = x + (size_t)b * NPTS * lda;
    int tid  = threadIdx.x;
    int lrow = tid >> 1, lk8 = (tid & 1) * 8;
    int tx = tid & 15, ty = tid >> 4;
    ull acc2[8][4];
    #pragma unroll
    for (int r = 0; r < 8; r++)
        #pragma unroll
        for (int q = 0; q < 4; q++) acc2[r][q] = 0ull;

    int ar = m0 + lrow, br = n0 + lrow;
    float ra[8], rb[8];
    #pragma unroll
    for (int q = 0; q < 8; q++) {
        int k = lk8 + q;
        ra[q] = (ar < NPTS && k < C) ? xb[(size_t)ar * lda + k] : 0.f;
        rb[q] = (br < NPTS && k < C) ? xb[(size_t)br * lda + k] : 0.f;
    }
    #pragma unroll
    for (int q = 0; q < 8; q++) {
        As[0][(lk8 + q) * 132 + lrow] = ra[q];
        Bs[0][(lk8 + q) * 132 + lrow] = rb[q];
    }
    __syncthreads();

    int buf = 0;
    for (int k0 = 0; k0 < C; k0 += 16) {
        int nk = k0 + 16;
        if (nk < C) {
            #pragma unroll
            for (int q = 0; q < 8; q++) {
                int k = nk + lk8 + q;
                ra[q] = (ar < NPTS && k < C) ? xb[(size_t)ar * lda + k] : 0.f;
                rb[q] = (br < NPTS && k < C) ? xb[(size_t)br * lda + k] : 0.f;
            }
        }
        const float* Ab = As[buf];
        const float* Bb = Bs[buf];
        #pragma unroll
        for (int kk = 0; kk < 16; kk++) {
            float a[8];
            *(float4*)&a[0] = *(const float4*)&Ab[kk * 132 + ty * 8];
            *(float4*)&a[4] = *(const float4*)&Ab[kk * 132 + ty * 8 + 4];
            ull bp[4];
            {
                ulonglong2 t0 = *(const ulonglong2*)&Bb[kk * 132 + tx * 8];
                ulonglong2 t1 = *(const ulonglong2*)&Bb[kk * 132 + tx * 8 + 4];
                bp[0] = t0.x; bp[1] = t0.y; bp[2] = t1.x; bp[3] = t1.y;
            }
            #pragma unroll
            for (int r = 0; r < 8; r++) {
                ull ap = pk2(a[r]);
                #pragma unroll
                for (int q = 0; q < 4; q++) fma2(acc2[r][q], ap, bp[q]);
            }
        }
        if (nk < C) {
            int nb = buf ^ 1;
            #pragma unroll
            for (int q = 0; q < 8; q++) {
                As[nb][(lk8 + q) * 132 + lrow] = ra[q];
                Bs[nb][(lk8 + q) * 132 + lrow] = rb[q];
            }
            __syncthreads();
            buf = nb;
        }
    }
    float* Gb = G + (size_t)b * NPTS * NPTS;
    #pragma unroll
    for (int r = 0; r < 8; r++) {
        int i = m0 + ty * 8 + r;
        if (i >= NPTS) continue;
        #pragma unroll
        for (int q = 0; q < 4; q++) {
            float lo, hi;
            unpk(acc2[r][q], lo, hi);
            int j0 = n0 + tx * 8 + 2 * q;
            int j1 = j0 + 1;
            if (j0 < NPTS) {
                Gb[(size_t)i * NPTS + j0] = lo;
                if (ti != tj) Gb[(size_t)j0 * NPTS + i] = lo;
                else if (i == j0) g_sq[b * NPTS + i] = lo;
            }
            if (j1 < NPTS) {
                Gb[(size_t)i * NPTS + j1] = hi;
                if (ti != tj) Gb[(size_t)j1 * NPTS + i] = hi;
                else if (i == j1) g_sq[b * NPTS + i] = hi;
            }
        }
    }
}

// ---------------- warp-parallel top-8 (ties -> lowest idx), 8 nodes/block --------------
__global__ void __launch_bounds__(256)
topk_kernel(const float* __restrict__ G) {
    int warp = threadIdx.x >> 5, lane = threadIdx.x & 31;
    int node = blockIdx.x * 8 + warp;
    int b = node / NPTS, i = node - b * NPTS, base = b * NPTS;
    const float* Grow = G + ((size_t)b * NPTS + i) * NPTS;
    float sqi = g_sq[node];

    float val[8]; int idx[8];
    #pragma unroll
    for (int q = 0; q < 8; q++) { val[q] = 3.3e38f; idx[q] = 0x7FFFFFFF; }

    for (int j = lane; j < NPTS; j += 32) {
        float v = sqi + g_sq[base + j] - 2.f * Grow[j];
        bool lt = (v < val[7]) || (v == val[7] && j < idx[7]);
        if (lt) {
            val[7] = v; idx[7] = j;
            #pragma unroll
            for (int q = 7; q > 0; q--) {
                bool sw = (val[q] < val[q - 1]) ||
                          (val[q] == val[q - 1] && idx[q] < idx[q - 1]);
                if (sw) {
                    float tv = val[q]; val[q] = val[q - 1]; val[q - 1] = tv;
                    int ti = idx[q]; idx[q] = idx[q - 1]; idx[q - 1] = ti;
                }
            }
        }
    }

    #pragma unroll
    for (int kk = 0; kk < KNN; kk++) {
        float bv = val[0]; int bi = idx[0];
        #pragma unroll
        for (int o = 16; o; o >>= 1) {
            float ov = __shfl_xor_sync(0xFFFFFFFFu, bv, o);
            int   oi = __shfl_xor_sync(0xFFFFFFFFu, bi, o);
            if (ov < bv || (ov == bv && oi < bi)) { bv = ov; bi = oi; }
        }
        if (lane == 0) g_idx[node * KNN + kk] = base + bi;
        if (idx[0] == bi && val[0] == bv) {
            #pragma unroll
            for (int q = 0; q < 7; q++) { val[q] = val[q + 1]; idx[q] = idx[q + 1]; }
            val[7] = 3.3e38f; idx[7] = 0x7FFFFFFF;
        }
    }
}

// -------- fused edge GEMM via bf16-split tensor-core mma ------------------------------
// A[128 edges x H] = relu(U[i]+V[j]+b1) built on the fly, split to (hi,lo) bf16.
// B[H x 128 cols] = W2 split to (hi,lo). acc += Ah*Bh + Ah*Bl + Al*Bh (fp32).
// Epilogue: max over the 8 edges of each node (shfl reduce) + b2.
__global__ void __launch_bounds__(256, 2)
fused_edge_mma(const float* __restrict__ U, const float* __restrict__ V,
               const float* __restrict__ b1, const float* __restrict__ W2,
               const float* __restrict__ b2, float* __restrict__ out,
               int ldo, float* __restrict__ outc, int H, int H2) {
    __shared__ uint Ah[2][128 * 8];
    __shared__ uint Al[2][128 * 8];
    __shared__ uint Bh[2][128 * 8];
    __shared__ uint Bl[2][128 * 8];
    __shared__ float sb1[256];
    int tid = threadIdx.x;
    int m0 = blockIdx.x * 128, n0 = blockIdx.y * 128;
    if (tid < H) sb1[tid] = b1[tid];

    int warp = tid >> 5, lane = tid & 31;
    int lp = lane & 3, lq = lane >> 2;
    int wm = warp & 3, wn = warp >> 2;

    float cf[2][8][4];
    #pragma unroll
    for (int mt = 0; mt < 2; mt++)
        #pragma unroll
        for (int nt = 0; nt < 8; nt++)
            #pragma unroll
            for (int q = 0; q < 4; q++) cf[mt][nt][q] = 0.f;

    // A loader mapping: row = tid>>1 (0..127), 8 k's at (tid&1)*8
    int arow = tid >> 1, ak8 = (tid & 1) * 8, kpb = (tid & 1) * 4;
    int e = m0 + arow;
    const float* Urow = U + (size_t)(e >> 3) * H;
    const float* Vrow = V + (size_t)g_idx[e] * H;
    // B loader mapping: kpair = tid&7 (0..7), 4 n's at (tid>>3)*4
    int bkp = tid & 7, bn4 = (tid >> 3) * 4;

    float ru[8], rv[8], rw0[4], rw1[4];
    // ---- load chunk 0 into regs ----
    {
        float4 u0 = *(const float4*)&Urow[ak8];
        float4 u1 = *(const float4*)&Urow[ak8 + 4];
        float4 v0 = *(const float4*)&Vrow[ak8];
        float4 v1 = *(const float4*)&Vrow[ak8 + 4];
        ru[0]=u0.x; ru[1]=u0.y; ru[2]=u0.z; ru[3]=u0.w;
        ru[4]=u1.x; ru[5]=u1.y; ru[6]=u1.z; ru[7]=u1.w;
        rv[0]=v0.x; rv[1]=v0.y; rv[2]=v0.z; rv[3]=v0.w;
        rv[4]=v1.x; rv[5]=v1.y; rv[6]=v1.z; rv[7]=v1.w;
        const float* W0 = W2 + (size_t)(2 * bkp) * H2;
        const float* W1 = W0 + H2;
        int gn = n0 + bn4;
        if (gn + 3 < H2) {
            float4 w0 = *(const float4*)&W0[gn];
            float4 w1 = *(const float4*)&W1[gn];
            rw0[0]=w0.x; rw0[1]=w0.y; rw0[2]=w0.z; rw0[3]=w0.w;
            rw1[0]=w1.x; rw1[1]=w1.y; rw1[2]=w1.z; rw1[3]=w1.w;
        } else {
            #pragma unroll
            for (int i = 0; i < 4; i++) {
                int n = gn + i;
                rw0[i] = (n < H2) ? W0[n] : 0.f;
                rw1[i] = (n < H2) ? W1[n] : 0.f;
            }
        }
    }
    __syncthreads();   // sb1 ready
    // ---- stage chunk 0 into smem buf 0 ----
    #pragma unroll
    for (int p = 0; p < 4; p++) {
        float f0 = fmaxf(ru[2*p]   + rv[2*p]   + sb1[ak8 + 2*p],   0.f);
        float f1 = fmaxf(ru[2*p+1] + rv[2*p+1] + sb1[ak8 + 2*p+1], 0.f);
        uint hp, lo_p;
        bsplit2(f0, f1, hp, lo_p);
        Ah[0][arow * 8 + kpb + p] = hp;
        Al[0][arow * 8 + kpb + p] = lo_p;
    }
    #pragma unroll
    for (int i = 0; i < 4; i++) {
        uint hp, lo_p;
        bsplit2(rw0[i], rw1[i], hp, lo_p);
        Bh[0][(bn4 + i) * 8 + bkp] = hp;
        Bl[0][(bn4 + i) * 8 + bkp] = lo_p;
    }
    __syncthreads();

    int buf = 0;
    for (int k0 = 0; k0 < H; k0 += 16) {
        int nk = k0 + 16;
        if (nk < H) {
            float4 u0 = *(const float4*)&Urow[nk + ak8];
            float4 u1 = *(const float4*)&Urow[nk + ak8 + 4];
            float4 v0 = *(const float4*)&Vrow[nk + ak8];
            float4 v1 = *(const float4*)&Vrow[nk + ak8 + 4];
            ru[0]=u0.x; ru[1]=u0.y; ru[2]=u0.z; ru[3]=u0.w;
            ru[4]=u1.x; ru[5]=u1.y; ru[6]=u1.z; ru[7]=u1.w;
            rv[0]=v0.x; rv[1]=v0.y; rv[2]=v0.z; rv[3]=v0.w;
            rv[4]=v1.x; rv[5]=v1.y; rv[6]=v1.z; rv[7]=v1.w;
            const float* W0 = W2 + (size_t)(nk + 2 * bkp) * H2;
            const float* W1 = W0 + H2;
            int gn = n0 + bn4;
            if (gn + 3 < H2) {
                float4 w0 = *(const float4*)&W0[gn];
                float4 w1 = *(const float4*)&W1[gn];
                rw0[0]=w0.x; rw0[1]=w0.y; rw0[2]=w0.z; rw0[3]=w0.w;
                rw1[0]=w1.x; rw1[1]=w1.y; rw1[2]=w1.z; rw1[3]=w1.w;
            } else {
                #pragma unroll
                for (int i = 0; i < 4; i++) {
                    int n = gn + i;
                    rw0[i] = (n < H2) ? W0[n] : 0.f;
                    rw1[i] = (n < H2) ? W1[n] : 0.f;
                }
            }
        }
        // ---- mma on current buffer ----
        #pragma unroll
        for (int mt = 0; mt < 2; mt++) {
            int row = wm * 32 + mt * 16 + lq;
            int ai = row * 8 + lp;
            uint ah0 = Ah[buf][ai],     ah1 = Ah[buf][ai + 64];
            uint ah2 = Ah[buf][ai + 4], ah3 = Ah[buf][ai + 68];
            uint al0 = Al[buf][ai],     al1 = Al[buf][ai + 64];
            uint al2 = Al[buf][ai + 4], al3 = Al[buf][ai + 68];
            #pragma unroll
            for (int nt = 0; nt < 8; nt++) {
                int n = wn * 64 + nt * 8 + lq;
                int bi = n * 8 + lp;
                uint bh0 = Bh[buf][bi], bh1 = Bh[buf][bi + 4];
                uint bl0 = Bl[buf][bi], bl1 = Bl[buf][bi + 4];
                MMA_BF16(cf[mt][nt], ah0, ah1, ah2, ah3, bh0, bh1);
                MMA_BF16(cf[mt][nt], ah0, ah1, ah2, ah3, bl0, bl1);
                MMA_BF16(cf[mt][nt], al0, al1, al2, al3, bh0, bh1);
            }
        }
        if (nk < H) {
            int nb = buf ^ 1;
            #pragma unroll
            for (int p = 0; p < 4; p++) {
                float f0 = fmaxf(ru[2*p]   + rv[2*p]   + sb1[nk + ak8 + 2*p],   0.f);
                float f1 = fmaxf(ru[2*p+1] + rv[2*p+1] + sb1[nk + ak8 + 2*p+1], 0.f);
                uint hp, lo_p;
                bsplit2(f0, f1, hp, lo_p);
                Ah[nb][arow * 8 + kpb + p] = hp;
                Al[nb][arow * 8 + kpb + p] = lo_p;
            }
            #pragma unroll
            for (int i = 0; i < 4; i++) {
                uint hp, lo_p;
                bsplit2(rw0[i], rw1[i], hp, lo_p);
                Bh[nb][(bn4 + i) * 8 + bkp] = hp;
                Bl[nb][(bn4 + i) * 8 + bkp] = lo_p;
            }
            __syncthreads();
            buf = nb;
        }
    }

    // ---- epilogue: max over 8 rows (= node's 8 edges) via shfl, then +b2 ----
    #pragma unroll
    for (int mt = 0; mt < 2; mt++) {
        int nodeA = ((m0 + wm * 32 + mt * 16) >> 3);
        int nodeB = nodeA + 1;
        #pragma unroll
        for (int nt = 0; nt < 8; nt++) {
            float v0 = cf[mt][nt][0], v1 = cf[mt][nt][1];
            float v2 = cf[mt][nt][2], v3 = cf[mt][nt][3];
            #pragma unroll
            for (int o = 4; o < 32; o <<= 1) {
                v0 = fmaxf(v0, __shfl_xor_sync(0xFFFFFFFFu, v0, o));
                v1 = fmaxf(v1, __shfl_xor_sync(0xFFFFFFFFu, v1, o));
                v2 = fmaxf(v2, __shfl_xor_sync(0xFFFFFFFFu, v2, o));
                v3 = fmaxf(v3, __shfl_xor_sync(0xFFFFFFFFu, v3, o));
            }
            if (lane < 4) {
                int c0 = n0 + wn * 64 + nt * 8 + 2 * lane;
                int c1 = c0 + 1;
                if (c0 < H2) {
                    float a = v0 + b2[c0];
                    float b = v2 + b2[c0];
                    out[(size_t)nodeA * ldo + c0] = a;
                    out[(size_t)nodeB * ldo + c0] = b;
                    if (outc) {
                        outc[(size_t)nodeA * H2 + c0] = a;
                        outc[(size_t)nodeB * H2 + c0] = b;
                    }
                }
                if (c1 < H2) {
                    float a = v1 + b2[c1];
                    float b = v3 + b2[c1];
                    out[(size_t)nodeA * ldo + c1] = a;
                    out[(size_t)nodeB * ldo + c1] = b;
                    if (outc) {
                        outc[(size_t)nodeA * H2 + c1] = a;
                        outc[(size_t)nodeB * H2 + c1] = b;
                    }
                }
            }
        }
    }
}

// ------------- generic fp32 GEMM (64x64, 4x4, f32x2, double-buffered) ------------------
__global__ void __launch_bounds__(256, 2)
gemm_kernel(const float* __restrict__ A, int lda,
            const float* __restrict__ B, int ldb,
            float* __restrict__ C, int ldc,
            int M, int N, int K,
            const float* __restrict__ bias, int dorelu) {
    __shared__ __align__(16) float As[2][16 * 68];
    __shared__ __align__(16) float Bs[2][16 * 68];
    int tid = threadIdx.x;
    int tx = tid & 15, ty = tid >> 4;
    int m0 = blockIdx.x * 64, n0 = blockIdx.y * 64;
    ull acc2[4][2];
    #pragma unroll
    for (int r = 0; r < 4; r++) { acc2[r][0] = 0ull; acc2[r][1] = 0ull; }

    int la_m = tid >> 2;
    int la_k = (tid & 3) << 2;
    int lb_k = tid >> 4;
    int lb_n = (tid & 15) << 2;
    int am = m0 + la_m;

    float ra[4], rbv[4];
    #pragma unroll
    for (int q = 0; q < 4; q++) {
        int ak = la_k + q;
        ra[q] = (am < M && ak < K) ? A[(size_t)am * lda + ak] : 0.f;
        int bn = n0 + lb_n + q;
        rbv[q] = (lb_k < K && bn < N) ? B[(size_t)lb_k * ldb + bn] : 0.f;
    }
    #pragma unroll
    for (int q = 0; q < 4; q++) {
        As[0][(la_k + q) * 68 + la_m] = ra[q];
        Bs[0][lb_k * 68 + lb_n + q] = rbv[q];
    }
    __syncthreads();

    int buf = 0;
    for (int k0 = 0; k0 < K; k0 += 16) {
        int nk = k0 + 16;
        if (nk < K) {
            #pragma unroll
            for (int q = 0; q < 4; q++) {
                int ak = nk + la_k + q;
                ra[q] = (am < M && ak < K) ? A[(size_t)am * lda + ak] : 0.f;
                int bn = n0 + lb_n + q;
                int bk = nk + lb_k;
                rbv[q] = (bk < K && bn < N) ? B[(size_t)bk * ldb + bn] : 0.f;
            }
        }
        const float* Ab = As[buf];
        const float* Bb = Bs[buf];
        #pragma unroll
        for (int kk = 0; kk < 16; kk++) {
            float4 af = *(const float4*)&Ab[kk * 68 + (ty << 2)];
            ulonglong2 bt = *(const ulonglong2*)&Bb[kk * 68 + (tx << 2)];
            float a[4] = {af.x, af.y, af.z, af.w};
            #pragma unroll
            for (int r = 0; r < 4; r++) {
                ull ap = pk2(a[r]);
                fma2(acc2[r][0], ap, bt.x);
                fma2(acc2[r][1], ap, bt.y);
            }
        }
        if (nk < K) {
            int nb = buf ^ 1;
            #pragma unroll
            for (int q = 0; q < 4; q++) {
                As[nb][(la_k + q) * 68 + la_m] = ra[q];
                Bs[nb][lb_k * 68 + lb_n + q] = rbv[q];
            }
            __syncthreads();
            buf = nb;
        }
    }

    #pragma unroll
    for (int r = 0; r < 4; r++) {
        int m = m0 + (ty << 2) + r;
        if (m >= M) continue;
        float av[4];
        unpk(acc2[r][0], av[0], av[1]);
        unpk(acc2[r][1], av[2], av[3]);
        #pragma unroll
        for (int c = 0; c < 4; c++) {
            int n = n0 + (tx << 2) + c;
            if (n >= N) continue;
            float v = av[c];
            if (bias) v += bias[n];
            if (dorelu) v = fmaxf(v, 0.f);
            C[(size_t)m * ldc + n] = v;
        }
    }
}

// ------------- dual GEMM (double-buffered): Uo = A@(B1 - sub*B2), Vo = A@B2 ------------
__global__ void __launch_bounds__(256, 2)
gemm_uv_kernel(const float* __restrict__ A, int lda,
               const float* __restrict__ B1, const float* __restrict__ B2, int ldb,
               float* __restrict__ Uo, float* __restrict__ Vo, int ldu,
               int M, int N, int K, int sub) {
    __shared__ __align__(16) float As[2][16 * 68];
    __shared__ __align__(16) float B1s[2][16 * 68];
    __shared__ __align__(16) float B2s[2][16 * 68];
    int tid = threadIdx.x;
    int tx = tid & 15, ty = tid >> 4;
    int m0 = blockIdx.x * 64, n0 = blockIdx.y * 64;
    ull aU[4][2], aV[4][2];
    #pragma unroll
    for (int r = 0; r < 4; r++) {
        aU[r][0] = aU[r][1] = 0ull;
        aV[r][0] = aV[r][1] = 0ull;
    }
    int la_m = tid >> 2;
    int la_k = (tid & 3) << 2;
    int lb_k = tid >> 4;
    int lb_n = (tid & 15) << 2;
    int am = m0 + la_m;

    float ra[4], r1[4], r2[4];
    #pragma unroll
    for (int q = 0; q < 4; q++) {
        int ak = la_k + q;
        ra[q] = (am < M && ak < K) ? A[(size_t)am * lda + ak] : 0.f;
        int bn = n0 + lb_n + q;
        float v1 = 0.f, v2 = 0.f;
        if (lb_k < K && bn < N) {
            size_t o = (size_t)lb_k * ldb + bn;
            v1 = B1[o]; v2 = B2[o];
        }
        r1[q] = sub ? (v1 - v2) : v1;
        r2[q] = v2;
    }
    #pragma unroll
    for (int q = 0; q < 4; q++) {
        As[0][(la_k + q) * 68 + la_m] = ra[q];
        B1s[0][lb_k * 68 + lb_n + q] = r1[q];
        B2s[0][lb_k * 68 + lb_n + q] = r2[q];
    }
    __syncthreads();

    int buf = 0;
    for (int k0 = 0; k0 < K; k0 += 16) {
        int nk = k0 + 16;
        if (nk < K) {
            #pragma unroll
            for (int q = 0; q < 4; q++) {
                int ak = nk + la_k + q;
                ra[q] = (am < M && ak < K) ? A[(size_t)am * lda + ak] : 0.f;
                int bn = n0 + lb_n + q;
                int bk = nk + lb_k;
                float v1 = 0.f, v2 = 0.f;
                if (bk < K && bn < N) {
                    size_t o = (size_t)bk * ldb + bn;
                    v1 = B1[o]; v2 = B2[o];
                }
                r1[q] = sub ? (v1 - v2) : v1;
                r2[q] = v2;
            }
        }
        const float* Ab  = As[buf];
        const float* B1b = B1s[buf];
        const float* B2b = B2s[buf];
        #pragma unroll
        for (int kk = 0; kk < 16; kk++) {
            float4 af = *(const float4*)&Ab[kk * 68 + (ty << 2)];
            ulonglong2 b1t = *(const ulonglong2*)&B1b[kk * 68 + (tx << 2)];
            ulonglong2 b2t = *(const ulonglong2*)&B2b[kk * 68 + (tx << 2)];
            float a[4] = {af.x, af.y, af.z, af.w};
            #pragma unroll
            for (int r = 0; r < 4; r++) {
                ull ap = pk2(a[r]);
                fma2(aU[r][0], ap, b1t.x);
                fma2(aU[r][1], ap, b1t.y);
                fma2(aV[r][0], ap, b2t.x);
                fma2(aV[r][1], ap, b2t.y);
            }
        }
        if (nk < K) {
            int nb = buf ^ 1;
            #pragma unroll
            for (int q = 0; q < 4; q++) {
                As[nb][(la_k + q) * 68 + la_m] = ra[q];
                B1s[nb][lb_k * 68 + lb_n + q] = r1[q];
                B2s[nb][lb_k * 68 + lb_n + q] = r2[q];
            }
            __syncthreads();
            buf = nb;
        }
    }

    #pragma unroll
    for (int r = 0; r < 4; r++) {
        int m = m0 + (ty << 2) + r;
        if (m >= M) continue;
        float u[4], v[4];
        unpk(aU[r][0], u[0], u[1]); unpk(aU[r][1], u[2], u[3]);
        unpk(aV[r][0], v[0], v[1]); unpk(aV[r][1], v[2], v[3]);
        #pragma unroll
        for (int c = 0; c < 4; c++) {
            int n = n0 + (tx << 2) + c;
            if (n >= N) continue;
            Uo[(size_t)m * ldu + n] = u[c];
            Vo[(size_t)m * ldu + n] = v[c];
        }
    }
}

// ---------------- global max pool, stage 1: partial max over 40 nodes ------------------
__global__ void gmax1_kernel() {
    int b = blockIdx.x, g = blockIdx.y, c = threadIdx.x;
    const float* p = g_sf + ((size_t)(b * NPTS) + g * 40) * 128 + c;
    float m = -3.3e38f;
    #pragma unroll 8
    for (int n = 0; n < 40; n++) m = fmaxf(m, p[n * 128]);
    g_pmax[(b * 25 + g) * 128 + c] = m;
}

// ---------------- stage 2: finish max + hg = g @ ec_w1[256:384] + ec_b1 ----------------
__global__ void hg2_kernel(const float* __restrict__ w1, const float* __restrict__ b1) {
    __shared__ float sg[128];
    int b = blockIdx.x, c = threadIdx.x;
    float m = -3.3e38f;
    #pragma unroll
    for (int g = 0; g < 25; g++) m = fmaxf(m, g_pmax[(b * 25 + g) * 128 + c]);
    sg[c] = m;
    __syncthreads();
    float s = b1[c];
    #pragma unroll 4
    for (int d = 0; d < 128; d++) s += sg[d] * w1[(256 + d) * 128 + c];
    g_hg[b * 128 + c] = s;
}

// ---------------- pair kernel: 64x64 tile, 4x4 pairs/thread ----------------
__global__ void __launch_bounds__(256)
pair_kernel(const float* __restrict__ w2, const float* __restrict__ b2,
            float* __restrict__ out) {
    int bx = blockIdx.x, by = blockIdx.y;
    if (bx < by) return;
    int b = blockIdx.z;
    extern __shared__ float ps[];
    float* s_hi = ps;
    float* s_hj = ps + 64 * 132;
    float* s_w  = ps + 2 * 64 * 132;

    int tid = threadIdx.y * 16 + threadIdx.x;
    int bi0 = by * 64, bj0 = bx * 64;

    for (int t = tid; t < 64 * 32; t += 256) {
        int r = t >> 5, c4 = (t & 31) << 2;
        int gi = bi0 + r;
        float4 v = make_float4(0.f, 0.f, 0.f, 0.f);
        if (gi < NPTS) v = *(const float4*)&g_hi[((size_t)(b * NPTS + gi)) * 128 + c4];
        *(float4*)&s_hi[r * 132 + c4] = v;
        int gj = bj0 + r;
        float4 u = make_float4(0.f, 0.f, 0.f, 0.f);
        if (gj < NPTS) {
            u = *(const float4*)&g_hjg[((size_t)(b * NPTS + gj)) * 128 + c4];
            float4 hgv = *(const float4*)&g_hg[b * 128 + c4];
            u.x += hgv.x; u.y += hgv.y; u.z += hgv.z; u.w += hgv.w;
        }
        *(float4*)&s_hj[r * 132 + c4] = u;
    }
    if (tid < 32) *(float4*)&s_w[tid * 4] = *(const float4*)&w2[tid * 4];
    __syncthreads();

    int ri0 = threadIdx.y * 4, cj0 = threadIdx.x * 4;
    float acc[4][4] = {};
    for (int c4 = 0; c4 < 128; c4 += 4) {
        float4 w = *(const float4*)&s_w[c4];
        float4 A[4], H[4];
        #pragma unroll
        for (int r = 0; r < 4; r++) A[r] = *(const float4*)&s_hi[(ri0 + r) * 132 + c4];
        #pragma unroll
        for (int c = 0; c < 4; c++) H[c] = *(const float4*)&s_hj[(cj0 + c) * 132 + c4];
        #pragma unroll
        for (int r = 0; r < 4; r++)
            #pragma unroll
            for (int c = 0; c < 4; c++) {
                acc[r][c] += fmaxf(A[r].x + H[c].x, 0.f) * w.x
                           + fmaxf(A[r].y + H[c].y, 0.f) * w.y
                           + fmaxf(A[r].z + H[c].z, 0.f) * w.z
                           + fmaxf(A[r].w + H[c].w, 0.f) * w.w;
            }
    }

    float bias2 = b2[0];
    #pragma unroll
    for (int r = 0; r < 4; r++) {
        int gi = bi0 + ri0 + r;
        #pragma unroll
        for (int c = 0; c < 4; c++) {
            int gj = bj0 + cj0 + c;
            if (gj < NPTS && gi < gj) {
                float m = acc[r][c] + bias2;
                int p = gi * (NPTS - 1) - (gi * (gi - 1)) / 2 + (gj - gi - 1);
                int off = b * NPAIR + p;
                out[off] = 1.f / (1.f + __expf(-m));
                out[BATCH * NPAIR + off] = m;
            }
        }
    }
}

// ============================ host side ============================
static void* sym_addr(const void* s) {
    void* p = nullptr;
    cudaGetSymbolAddress(&p, s);
    return p;
}

extern "C" void kernel_launch(void* const* d_in, const int* in_sizes, int n_in,
                              void* d_out, int out_size) {
    const float* in[21];
    for (int i = 0; i < 21; i++) in[i] = (const float*)d_in[i];
    const float* pos   = in[0];
    const float* c1_w1 = in[1];  const float* c1_b1 = in[2];
    const float* c1_w2 = in[3];  const float* c1_b2 = in[4];
    const float* c2_w1 = in[5];  const float* c2_b1 = in[6];
    const float* c2_w2 = in[7];  const float* c2_b2 = in[8];
    const float* c3_w1 = in[9];  const float* c3_b1 = in[10];
    const float* c3_w2 = in[11]; const float* c3_b2 = in[12];
    const float* sm_w1 = in[13]; const float* sm_b1 = in[14];
    const float* sm_w2 = in[15]; const float* sm_b2 = in[16];
    const float* ec_w1 = in[17]; const float* ec_b1 = in[18];
    const float* ec_w2 = in[19]; const float* ec_b2 = in[20];

    float* x1  = (float*)sym_addr(g_x1);
    float* x2  = (float*)sym_addr(g_x2);
    float* U   = (float*)sym_addr(g_U);
    float* V   = (float*)sym_addr(g_V);
    float* G   = (float*)sym_addr(g_G);
    float* cat = (float*)sym_addr(g_cat);
    float* smh = (float*)sym_addr(g_smh);
    float* sf  = (float*)sym_addr(g_sf);
    float* hi  = (float*)sym_addr(g_hi);
    float* hjg = (float*)sym_addr(g_hjg);

    cudaStream_t s1;
    cudaStreamCreateWithFlags(&s1, cudaStreamNonBlocking);
    cudaEvent_t ev[10];
    for (int i = 0; i < 10; i++) cudaEventCreateWithFlags(&ev[i], cudaEventDisableTiming);
    int ei = 0;

    struct LayerP {
        const float* x; int lda, C, H, H2;
        const float* w1; const float* b1; const float* w2; const float* b2;
        float* outp; int ldo; float* outc;
    } L[3] = {
        { pos, 3,   3,   16,  32,  c1_w1, c1_b1, c1_w2, c1_b2, cat + 0,   672, x1 },
        { x1,  32,  32,  64,  128, c2_w1, c2_b1, c2_w2, c2_b2, cat + 32,  672, x2 },
        { x2,  128, 128, 256, 512, c3_w1, c3_b1, c3_w2, c3_b2, cat + 160, 672, nullptr },
    };

    for (int l = 0; l < 3; l++) {
        cudaEventRecord(ev[ei], 0);
        cudaStreamWaitEvent(s1, ev[ei], 0); ei++;
        dim3 guv((BNODES + 63) / 64, (L[l].H + 63) / 64);
        gemm_uv_kernel<<<guv, 256, 0, s1>>>(L[l].x, L[l].lda, L[l].w1,
                                            L[l].w1 + (size_t)L[l].C * L[l].H, L[l].H,
                                            U, V, L[l].H, BNODES, L[l].H, L[l].C, 1);
        cudaEventRecord(ev[ei], s1);

        xxt_kernel<<<dim3(36, BATCH), 256>>>(L[l].x, L[l].lda, L[l].C, G);
        topk_kernel<<<BNODES / 8, 256>>>(G);

        cudaStreamWaitEvent(0, ev[ei], 0); ei++;
        fused_edge_mma<<<dim3(125, (L[l].H2 + 127) / 128), 256>>>(
            U, V, L[l].b1, L[l].w2, L[l].b2, L[l].outp, L[l].ldo, L[l].outc,
            L[l].H, L[l].H2);
    }

    // sm MLP: [2000,672] -> relu 256 -> 128
    {
        dim3 g1((BNODES + 63) / 64, 4);
        gemm_kernel<<<g1, 256>>>(cat, 672, sm_w1, 256, smh, 256, BNODES, 256, 672, sm_b1, 1);
        dim3 g2((BNODES + 63) / 64, 2);
        gemm_kernel<<<g2, 256>>>(smh, 256, sm_w2, 128, sf, 128, BNODES, 128, 256, sm_b2, 0);
    }

    // fork: hi/hjg dual GEMM on s1, gmax(2-stage)+hg on main
    cudaEventRecord(ev[ei], 0);
    cudaStreamWaitEvent(s1, ev[ei], 0); ei++;
    dim3 ghh((BNODES + 63) / 64, 2);
    gemm_uv_kernel<<<ghh, 256, 0, s1>>>(sf, 128, ec_w1 + 128 * 128, ec_w1, 128,
                                        hjg, hi, 128, BNODES, 128, 128, 0);
    cudaEventRecord(ev[ei], s1);

    gmax1_kernel<<<dim3(BATCH, 25), 128>>>();
    hg2_kernel<<<BATCH, 128>>>(ec_w1, ec_b1);

    cudaStreamWaitEvent(0, ev[ei], 0); ei++;

    // fused pair stage -> d_out = [pair_prob (B*P), mlp_out (B*P)]
    size_t psmem = (2 * 64 * 132 + 128) * sizeof(float);
    cudaFuncSetAttribute(pair_kernel, cudaFuncAttributeMaxDynamicSharedMemorySize, (int)psmem);
    pair_kernel<<<dim3(16, 16, BATCH), dim3(16, 16), psmem>>>(ec_w2, ec_b2, (float*)d_out);
}

// round 12
// speedup vs baseline: 1.2789x; 1.0327x over previous
#include <cuda_runtime.h>
#include <cuda_bf16.h>
#include <math.h>

#define NPTS   1000
#define BATCH  2
#define BNODES 2000
#define KNN    8
#define NEDGE  (BNODES*KNN)
#define NPAIR  499500   // NPTS*(NPTS-1)/2

typedef unsigned long long ull;
typedef unsigned int uint;

// packed f32x2 helpers (Blackwell: fma.rn.f32x2 — PTX-only)
__device__ __forceinline__ ull pk2(float x) {
    ull r; asm("mov.b64 %0, {%1, %1};" : "=l"(r) : "f"(x)); return r;
}
__device__ __forceinline__ void fma2(ull& d, ull a, ull b) {
    asm("fma.rn.f32x2 %0, %1, %2, %0;" : "+l"(d) : "l"(a), "l"(b));
}
__device__ __forceinline__ void unpk(ull v, float& lo, float& hi) {
    asm("mov.b64 {%0, %1}, %2;" : "=f"(lo), "=f"(hi) : "l"(v));
}

// bf16 split helpers
__device__ __forceinline__ uint bfpack2(__nv_bfloat16 lo, __nv_bfloat16 hi) {
    return ((uint)__bfloat16_as_ushort(hi) << 16) | (uint)__bfloat16_as_ushort(lo);
}
__device__ __forceinline__ void bsplit2(float f0, float f1, uint& hp, uint& lp) {
    __nv_bfloat16 h0 = __float2bfloat16_rn(f0);
    __nv_bfloat16 h1 = __float2bfloat16_rn(f1);
    float l0 = f0 - __bfloat162float(h0);
    float l1 = f1 - __bfloat162float(h1);
    hp = bfpack2(h0, h1);
    lp = bfpack2(__float2bfloat16_rn(l0), __float2bfloat16_rn(l1));
}

#define MMA_BF16(c, a0, a1, a2, a3, b0, b1)                                     \
    asm volatile("mma.sync.aligned.m16n8k16.row.col.f32.bf16.bf16.f32 "          \
                 "{%0,%1,%2,%3}, {%4,%5,%6,%7}, {%8,%9}, {%0,%1,%2,%3};"         \
                 : "+f"((c)[0]), "+f"((c)[1]), "+f"((c)[2]), "+f"((c)[3])        \
                 : "r"(a0), "r"(a1), "r"(a2), "r"(a3), "r"(b0), "r"(b1))

// ---------------- scratch (static __device__; no allocations) ----------------
__device__ float g_sq[BNODES];
__device__ int   g_idx[NEDGE];
__device__ __align__(16) float g_x1[BNODES*32];
__device__ __align__(16) float g_x2[BNODES*128];
__device__ __align__(16) float g_U[BNODES*256];
__device__ __align__(16) float g_V[BNODES*256];
__device__ __align__(16) float g_G[BATCH*NPTS*NPTS];
__device__ __align__(16) float g_cat[BNODES*672];
__device__ __align__(16) float g_smh[BNODES*256];
__device__ __align__(16) float g_sf[BNODES*128];
__device__ __align__(16) float g_hi[BNODES*128];
__device__ __align__(16) float g_hjg[BNODES*128];
__device__ __align__(16) float g_hg[BATCH*128];
__device__ __align__(16) float g_pmax[BATCH*25*128];

// -------- X @ X^T, symmetric: 36 upper tiles per batch, mirror store ------------------
__global__ void __launch_bounds__(256, 2)
xxt_kernel(const float* __restrict__ x, int lda, int C, float* __restrict__ G) {
    __shared__ __align__(16) float As[2][16 * 132];
    __shared__ __align__(16) float Bs[2][16 * 132];
    int b = blockIdx.y;
    int t = blockIdx.x, ti = 0;
    while (t >= 8 - ti) { t -= 8 - ti; ti++; }
    int tj = ti + t;
    int m0 = ti * 128, n0 = tj * 128;
    const float* xb = x + (size_t)b * NPTS * lda;
    int tid  = threadIdx.x;
    int lrow = tid >> 1, lk8 = (tid & 1) * 8;
    int tx = tid & 15, ty = tid >> 4;
    ull acc2[8][4];
    #pragma unroll
    for (int r = 0; r < 8; r++)
        #pragma unroll
        for (int q = 0; q < 4; q++) acc2[r][q] = 0ull;

    int ar = m0 + lrow, br = n0 + lrow;
    float ra[8], rb[8];
    #pragma unroll
    for (int q = 0; q < 8; q++) {
        int k = lk8 + q;
        ra[q] = (ar < NPTS && k < C) ? xb[(size_t)ar * lda + k] : 0.f;
        rb[q] = (br < NPTS && k < C) ? xb[(size_t)br * lda + k] : 0.f;
    }
    #pragma unroll
    for (int q = 0; q < 8; q++) {
        As[0][(lk8 + q) * 132 + lrow] = ra[q];
        Bs[0][(lk8 + q) * 132 + lrow] = rb[q];
    }
    __syncthreads();

    int buf = 0;
    for (int k0 = 0; k0 < C; k0 += 16) {
        int nk = k0 + 16;
        if (nk < C) {
            #pragma unroll
            for (int q = 0; q < 8; q++) {
                int k = nk + lk8 + q;
                ra[q] = (ar < NPTS && k < C) ? xb[(size_t)ar * lda + k] : 0.f;
                rb[q] = (br < NPTS && k < C) ? xb[(size_t)br * lda + k] : 0.f;
            }
        }
        const float* Ab = As[buf];
        const float* Bb = Bs[buf];
        #pragma unroll
        for (int kk = 0; kk < 16; kk++) {
            float a[8];
            *(float4*)&a[0] = *(const float4*)&Ab[kk * 132 + ty * 8];
            *(float4*)&a[4] = *(const float4*)&Ab[kk * 132 + ty * 8 + 4];
            ull bp[4];
            {
                ulonglong2 t0 = *(const ulonglong2*)&Bb[kk * 132 + tx * 8];
                ulonglong2 t1 = *(const ulonglong2*)&Bb[kk * 132 + tx * 8 + 4];
                bp[0] = t0.x; bp[1] = t0.y; bp[2] = t1.x; bp[3] = t1.y;
            }
            #pragma unroll
            for (int r = 0; r < 8; r++) {
                ull ap = pk2(a[r]);
                #pragma unroll
                for (int q = 0; q < 4; q++) fma2(acc2[r][q], ap, bp[q]);
            }
        }
        if (nk < C) {
            int nb = buf ^ 1;
            #pragma unroll
            for (int q = 0; q < 8; q++) {
                As[nb][(lk8 + q) * 132 + lrow] = ra[q];
                Bs[nb][(lk8 + q) * 132 + lrow] = rb[q];
            }
            __syncthreads();
            buf = nb;
        }
    }
    float* Gb = G + (size_t)b * NPTS * NPTS;
    #pragma unroll
    for (int r = 0; r < 8; r++) {
        int i = m0 + ty * 8 + r;
        if (i >= NPTS) continue;
        #pragma unroll
        for (int q = 0; q < 4; q++) {
            float lo, hi;
            unpk(acc2[r][q], lo, hi);
            int j0 = n0 + tx * 8 + 2 * q;
            int j1 = j0 + 1;
            if (j0 < NPTS) {
                Gb[(size_t)i * NPTS + j0] = lo;
                if (ti != tj) Gb[(size_t)j0 * NPTS + i] = lo;
                else if (i == j0) g_sq[b * NPTS + i] = lo;
            }
            if (j1 < NPTS) {
                Gb[(size_t)i * NPTS + j1] = hi;
                if (ti != tj) Gb[(size_t)j1 * NPTS + i] = hi;
                else if (i == j1) g_sq[b * NPTS + i] = hi;
            }
        }
    }
}

// ---------------- warp-parallel top-8 (ties -> lowest idx), 8 nodes/block --------------
__global__ void __launch_bounds__(256)
topk_kernel(const float* __restrict__ G) {
    int warp = threadIdx.x >> 5, lane = threadIdx.x & 31;
    int node = blockIdx.x * 8 + warp;
    int b = node / NPTS, i = node - b * NPTS, base = b * NPTS;
    const float* Grow = G + ((size_t)b * NPTS + i) * NPTS;
    float sqi = g_sq[node];

    float val[8]; int idx[8];
    #pragma unroll
    for (int q = 0; q < 8; q++) { val[q] = 3.3e38f; idx[q] = 0x7FFFFFFF; }

    for (int j = lane; j < NPTS; j += 32) {
        float v = sqi + g_sq[base + j] - 2.f * Grow[j];
        bool lt = (v < val[7]) || (v == val[7] && j < idx[7]);
        if (lt) {
            val[7] = v; idx[7] = j;
            #pragma unroll
            for (int q = 7; q > 0; q--) {
                bool sw = (val[q] < val[q - 1]) ||
                          (val[q] == val[q - 1] && idx[q] < idx[q - 1]);
                if (sw) {
                    float tv = val[q]; val[q] = val[q - 1]; val[q - 1] = tv;
                    int ti = idx[q]; idx[q] = idx[q - 1]; idx[q - 1] = ti;
                }
            }
        }
    }

    #pragma unroll
    for (int kk = 0; kk < KNN; kk++) {
        float bv = val[0]; int bi = idx[0];
        #pragma unroll
        for (int o = 16; o; o >>= 1) {
            float ov = __shfl_xor_sync(0xFFFFFFFFu, bv, o);
            int   oi = __shfl_xor_sync(0xFFFFFFFFu, bi, o);
            if (ov < bv || (ov == bv && oi < bi)) { bv = ov; bi = oi; }
        }
        if (lane == 0) g_idx[node * KNN + kk] = base + bi;
        if (idx[0] == bi && val[0] == bv) {
            #pragma unroll
            for (int q = 0; q < 7; q++) { val[q] = val[q + 1]; idx[q] = idx[q + 1]; }
            val[7] = 3.3e38f; idx[7] = 0x7FFFFFFF;
        }
    }
}

// -------- fused edge GEMM via bf16-split tensor-core mma ------------------------------
__global__ void __launch_bounds__(256, 2)
fused_edge_mma(const float* __restrict__ U, const float* __restrict__ V,
               const float* __restrict__ b1, const float* __restrict__ W2,
               const float* __restrict__ b2, float* __restrict__ out,
               int ldo, float* __restrict__ outc, int H, int H2) {
    __shared__ uint Ah[2][128 * 8];
    __shared__ uint Al[2][128 * 8];
    __shared__ uint Bh[2][128 * 8];
    __shared__ uint Bl[2][128 * 8];
    __shared__ float sb1[256];
    int tid = threadIdx.x;
    int m0 = blockIdx.x * 128, n0 = blockIdx.y * 128;
    if (tid < H) sb1[tid] = b1[tid];

    int warp = tid >> 5, lane = tid & 31;
    int lp = lane & 3, lq = lane >> 2;
    int wm = warp & 3, wn = warp >> 2;

    float cf[2][8][4];
    #pragma unroll
    for (int mt = 0; mt < 2; mt++)
        #pragma unroll
        for (int nt = 0; nt < 8; nt++)
            #pragma unroll
            for (int q = 0; q < 4; q++) cf[mt][nt][q] = 0.f;

    int arow = tid >> 1, ak8 = (tid & 1) * 8, kpb = (tid & 1) * 4;
    int e = m0 + arow;
    const float* Urow = U + (size_t)(e >> 3) * H;
    const float* Vrow = V + (size_t)g_idx[e] * H;
    int bkp = tid & 7, bn4 = (tid >> 3) * 4;

    float ru[8], rv[8], rw0[4], rw1[4];
    {
        float4 u0 = *(const float4*)&Urow[ak8];
        float4 u1 = *(const float4*)&Urow[ak8 + 4];
        float4 v0 = *(const float4*)&Vrow[ak8];
        float4 v1 = *(const float4*)&Vrow[ak8 + 4];
        ru[0]=u0.x; ru[1]=u0.y; ru[2]=u0.z; ru[3]=u0.w;
        ru[4]=u1.x; ru[5]=u1.y; ru[6]=u1.z; ru[7]=u1.w;
        rv[0]=v0.x; rv[1]=v0.y; rv[2]=v0.z; rv[3]=v0.w;
        rv[4]=v1.x; rv[5]=v1.y; rv[6]=v1.z; rv[7]=v1.w;
        const float* W0 = W2 + (size_t)(2 * bkp) * H2;
        const float* W1 = W0 + H2;
        int gn = n0 + bn4;
        if (gn + 3 < H2) {
            float4 w0 = *(const float4*)&W0[gn];
            float4 w1 = *(const float4*)&W1[gn];
            rw0[0]=w0.x; rw0[1]=w0.y; rw0[2]=w0.z; rw0[3]=w0.w;
            rw1[0]=w1.x; rw1[1]=w1.y; rw1[2]=w1.z; rw1[3]=w1.w;
        } else {
            #pragma unroll
            for (int i = 0; i < 4; i++) {
                int n = gn + i;
                rw0[i] = (n < H2) ? W0[n] : 0.f;
                rw1[i] = (n < H2) ? W1[n] : 0.f;
            }
        }
    }
    __syncthreads();
    #pragma unroll
    for (int p = 0; p < 4; p++) {
        float f0 = fmaxf(ru[2*p]   + rv[2*p]   + sb1[ak8 + 2*p],   0.f);
        float f1 = fmaxf(ru[2*p+1] + rv[2*p+1] + sb1[ak8 + 2*p+1], 0.f);
        uint hp, lo_p;
        bsplit2(f0, f1, hp, lo_p);
        Ah[0][arow * 8 + kpb + p] = hp;
        Al[0][arow * 8 + kpb + p] = lo_p;
    }
    #pragma unroll
    for (int i = 0; i < 4; i++) {
        uint hp, lo_p;
        bsplit2(rw0[i], rw1[i], hp, lo_p);
        Bh[0][(bn4 + i) * 8 + bkp] = hp;
        Bl[0][(bn4 + i) * 8 + bkp] = lo_p;
    }
    __syncthreads();

    int buf = 0;
    for (int k0 = 0; k0 < H; k0 += 16) {
        int nk = k0 + 16;
        if (nk < H) {
            float4 u0 = *(const float4*)&Urow[nk + ak8];
            float4 u1 = *(const float4*)&Urow[nk + ak8 + 4];
            float4 v0 = *(const float4*)&Vrow[nk + ak8];
            float4 v1 = *(const float4*)&Vrow[nk + ak8 + 4];
            ru[0]=u0.x; ru[1]=u0.y; ru[2]=u0.z; ru[3]=u0.w;
            ru[4]=u1.x; ru[5]=u1.y; ru[6]=u1.z; ru[7]=u1.w;
            rv[0]=v0.x; rv[1]=v0.y; rv[2]=v0.z; rv[3]=v0.w;
            rv[4]=v1.x; rv[5]=v1.y; rv[6]=v1.z; rv[7]=v1.w;
            const float* W0 = W2 + (size_t)(nk + 2 * bkp) * H2;
            const float* W1 = W0 + H2;
            int gn = n0 + bn4;
            if (gn + 3 < H2) {
                float4 w0 = *(const float4*)&W0[gn];
                float4 w1 = *(const float4*)&W1[gn];
                rw0[0]=w0.x; rw0[1]=w0.y; rw0[2]=w0.z; rw0[3]=w0.w;
                rw1[0]=w1.x; rw1[1]=w1.y; rw1[2]=w1.z; rw1[3]=w1.w;
            } else {
                #pragma unroll
                for (int i = 0; i < 4; i++) {
                    int n = gn + i;
                    rw0[i] = (n < H2) ? W0[n] : 0.f;
                    rw1[i] = (n < H2) ? W1[n] : 0.f;
                }
            }
        }
        #pragma unroll
        for (int mt = 0; mt < 2; mt++) {
            int row = wm * 32 + mt * 16 + lq;
            int ai = row * 8 + lp;
            uint ah0 = Ah[buf][ai],     ah1 = Ah[buf][ai + 64];
            uint ah2 = Ah[buf][ai + 4], ah3 = Ah[buf][ai + 68];
            uint al0 = Al[buf][ai],     al1 = Al[buf][ai + 64];
            uint al2 = Al[buf][ai + 4], al3 = Al[buf][ai + 68];
            #pragma unroll
            for (int nt = 0; nt < 8; nt++) {
                int n = wn * 64 + nt * 8 + lq;
                int bi = n * 8 + lp;
                uint bh0 = Bh[buf][bi], bh1 = Bh[buf][bi + 4];
                uint bl0 = Bl[buf][bi], bl1 = Bl[buf][bi + 4];
                MMA_BF16(cf[mt][nt], ah0, ah1, ah2, ah3, bh0, bh1);
                MMA_BF16(cf[mt][nt], ah0, ah1, ah2, ah3, bl0, bl1);
                MMA_BF16(cf[mt][nt], al0, al1, al2, al3, bh0, bh1);
            }
        }
        if (nk < H) {
            int nb = buf ^ 1;
            #pragma unroll
            for (int p = 0; p < 4; p++) {
                float f0 = fmaxf(ru[2*p]   + rv[2*p]   + sb1[nk + ak8 + 2*p],   0.f);
                float f1 = fmaxf(ru[2*p+1] + rv[2*p+1] + sb1[nk + ak8 + 2*p+1], 0.f);
                uint hp, lo_p;
                bsplit2(f0, f1, hp, lo_p);
                Ah[nb][arow * 8 + kpb + p] = hp;
                Al[nb][arow * 8 + kpb + p] = lo_p;
            }
            #pragma unroll
            for (int i = 0; i < 4; i++) {
                uint hp, lo_p;
                bsplit2(rw0[i], rw1[i], hp, lo_p);
                Bh[nb][(bn4 + i) * 8 + bkp] = hp;
                Bl[nb][(bn4 + i) * 8 + bkp] = lo_p;
            }
            __syncthreads();
            buf = nb;
        }
    }

    #pragma unroll
    for (int mt = 0; mt < 2; mt++) {
        int nodeA = ((m0 + wm * 32 + mt * 16) >> 3);
        int nodeB = nodeA + 1;
        #pragma unroll
        for (int nt = 0; nt < 8; nt++) {
            float v0 = cf[mt][nt][0], v1 = cf[mt][nt][1];
            float v2 = cf[mt][nt][2], v3 = cf[mt][nt][3];
            #pragma unroll
            for (int o = 4; o < 32; o <<= 1) {
                v0 = fmaxf(v0, __shfl_xor_sync(0xFFFFFFFFu, v0, o));
                v1 = fmaxf(v1, __shfl_xor_sync(0xFFFFFFFFu, v1, o));
                v2 = fmaxf(v2, __shfl_xor_sync(0xFFFFFFFFu, v2, o));
                v3 = fmaxf(v3, __shfl_xor_sync(0xFFFFFFFFu, v3, o));
            }
            if (lane < 4) {
                int c0 = n0 + wn * 64 + nt * 8 + 2 * lane;
                int c1 = c0 + 1;
                if (c0 < H2) {
                    float a = v0 + b2[c0];
                    float b = v2 + b2[c0];
                    out[(size_t)nodeA * ldo + c0] = a;
                    out[(size_t)nodeB * ldo + c0] = b;
                    if (outc) {
                        outc[(size_t)nodeA * H2 + c0] = a;
                        outc[(size_t)nodeB * H2 + c0] = b;
                    }
                }
                if (c1 < H2) {
                    float a = v1 + b2[c1];
                    float b = v3 + b2[c1];
                    out[(size_t)nodeA * ldo + c1] = a;
                    out[(size_t)nodeB * ldo + c1] = b;
                    if (outc) {
                        outc[(size_t)nodeA * H2 + c1] = a;
                        outc[(size_t)nodeB * H2 + c1] = b;
                    }
                }
            }
        }
    }
}

// -------- generic GEMM via bf16-split mma: 64x64 tiles, C = relu?(A@B + bias) ---------
// A [M,K] row-major fp32, B [K,N] row-major fp32. K must be a multiple of 16.
__global__ void __launch_bounds__(256, 2)
gemm_mma64(const float* __restrict__ A, int lda,
           const float* __restrict__ B, int ldb,
           float* __restrict__ C, int ldc,
           int M, int N, int K,
           const float* __restrict__ bias, int dorelu) {
    __shared__ uint Ah[2][64 * 8];
    __shared__ uint Al[2][64 * 8];
    __shared__ uint Bh[2][64 * 8];
    __shared__ uint Bl[2][64 * 8];
    int tid = threadIdx.x;
    int m0 = blockIdx.x * 64, n0 = blockIdx.y * 64;

    int warp = tid >> 5, lane = tid & 31;
    int lp = lane & 3, lq = lane >> 2;
    int wm = warp & 1, wn = warp >> 1;   // 2 m-warps x 4 n-warps

    float cf[2][2][4];
    #pragma unroll
    for (int mt = 0; mt < 2; mt++)
        #pragma unroll
        for (int nt = 0; nt < 2; nt++)
            #pragma unroll
            for (int q = 0; q < 4; q++) cf[mt][nt][q] = 0.f;

    // A loader: row = tid>>2 (0..63), 4 k's at (tid&3)*4
    int arow = tid >> 2, akq = (tid & 3) * 4;
    int am = m0 + arow;
    const float* Arow = A + (size_t)am * lda;
    // B loader: n = tid&63, 4 k's at (tid>>6)*4
    int bn = tid & 63, bkq = (tid >> 6) * 4;
    int gn = n0 + bn;

    float ra[4], rbv[4];
    // prefetch tile 0
    {
        if (am < M) {
            float4 a0 = *(const float4*)&Arow[akq];
            ra[0]=a0.x; ra[1]=a0.y; ra[2]=a0.z; ra[3]=a0.w;
        } else { ra[0]=ra[1]=ra[2]=ra[3]=0.f; }
        #pragma unroll
        for (int q = 0; q < 4; q++)
            rbv[q] = (gn < N) ? B[(size_t)(bkq + q) * ldb + gn] : 0.f;
    }
    {
        uint hp, lo_p;
        bsplit2(ra[0], ra[1], hp, lo_p);
        Ah[0][arow * 8 + akq / 2] = hp;  Al[0][arow * 8 + akq / 2] = lo_p;
        bsplit2(ra[2], ra[3], hp, lo_p);
        Ah[0][arow * 8 + akq / 2 + 1] = hp;  Al[0][arow * 8 + akq / 2 + 1] = lo_p;
        bsplit2(rbv[0], rbv[1], hp, lo_p);
        Bh[0][bn * 8 + bkq / 2] = hp;  Bl[0][bn * 8 + bkq / 2] = lo_p;
        bsplit2(rbv[2], rbv[3], hp, lo_p);
        Bh[0][bn * 8 + bkq / 2 + 1] = hp;  Bl[0][bn * 8 + bkq / 2 + 1] = lo_p;
    }
    __syncthreads();

    int buf = 0;
    for (int k0 = 0; k0 < K; k0 += 16) {
        int nk = k0 + 16;
        if (nk < K) {
            if (am < M) {
                float4 a0 = *(const float4*)&Arow[nk + akq];
                ra[0]=a0.x; ra[1]=a0.y; ra[2]=a0.z; ra[3]=a0.w;
            } else { ra[0]=ra[1]=ra[2]=ra[3]=0.f; }
            #pragma unroll
            for (int q = 0; q < 4; q++)
                rbv[q] = (gn < N) ? B[(size_t)(nk + bkq + q) * ldb + gn] : 0.f;
        }
        #pragma unroll
        for (int mt = 0; mt < 2; mt++) {
            int row = wm * 32 + mt * 16 + lq;
            int ai = row * 8 + lp;
            uint ah0 = Ah[buf][ai],     ah1 = Ah[buf][ai + 64];
            uint ah2 = Ah[buf][ai + 4], ah3 = Ah[buf][ai + 68];
            uint al0 = Al[buf][ai],     al1 = Al[buf][ai + 64];
            uint al2 = Al[buf][ai + 4], al3 = Al[buf][ai + 68];
            #pragma unroll
            for (int nt = 0; nt < 2; nt++) {
                int n = wn * 16 + nt * 8 + lq;
                int bi = n * 8 + lp;
                uint bh0 = Bh[buf][bi], bh1 = Bh[buf][bi + 4];
                uint bl0 = Bl[buf][bi], bl1 = Bl[buf][bi + 4];
                MMA_BF16(cf[mt][nt], ah0, ah1, ah2, ah3, bh0, bh1);
                MMA_BF16(cf[mt][nt], ah0, ah1, ah2, ah3, bl0, bl1);
                MMA_BF16(cf[mt][nt], al0, al1, al2, al3, bh0, bh1);
            }
        }
        if (nk < K) {
            int nb = buf ^ 1;
            uint hp, lo_p;
            bsplit2(ra[0], ra[1], hp, lo_p);
            Ah[nb][arow * 8 + akq / 2] = hp;  Al[nb][arow * 8 + akq / 2] = lo_p;
            bsplit2(ra[2], ra[3], hp, lo_p);
            Ah[nb][arow * 8 + akq / 2 + 1] = hp;  Al[nb][arow * 8 + akq / 2 + 1] = lo_p;
            bsplit2(rbv[0], rbv[1], hp, lo_p);
            Bh[nb][bn * 8 + bkq / 2] = hp;  Bl[nb][bn * 8 + bkq / 2] = lo_p;
            bsplit2(rbv[2], rbv[3], hp, lo_p);
            Bh[nb][bn * 8 + bkq / 2 + 1] = hp;  Bl[nb][bn * 8 + bkq / 2 + 1] = lo_p;
            __syncthreads();
            buf = nb;
        }
    }

    // epilogue
    #pragma unroll
    for (int mt = 0; mt < 2; mt++) {
        #pragma unroll
        for (int nt = 0; nt < 2; nt++) {
            int row0 = m0 + wm * 32 + mt * 16 + lq;
            int col0 = n0 + wn * 16 + nt * 8 + 2 * lp;
            #pragma unroll
            for (int q = 0; q < 4; q++) {
                int m = row0 + (q >> 1) * 8;
                int n = col0 + (q & 1);
                if (m < M && n < N) {
                    float v = cf[mt][nt][q];
                    if (bias) v += bias[n];
                    if (dorelu) v = fmaxf(v, 0.f);
                    C[(size_t)m * ldc + n] = v;
                }
            }
        }
    }
}

// ------------- dual GEMM (double-buffered): Uo = A@(B1 - sub*B2), Vo = A@B2 ------------
__global__ void __launch_bounds__(256, 2)
gemm_uv_kernel(const float* __restrict__ A, int lda,
               const float* __restrict__ B1, const float* __restrict__ B2, int ldb,
               float* __restrict__ Uo, float* __restrict__ Vo, int ldu,
               int M, int N, int K, int sub) {
    __shared__ __align__(16) float As[2][16 * 68];
    __shared__ __align__(16) float B1s[2][16 * 68];
    __shared__ __align__(16) float B2s[2][16 * 68];
    int tid = threadIdx.x;
    int tx = tid & 15, ty = tid >> 4;
    int m0 = blockIdx.x * 64, n0 = blockIdx.y * 64;
    ull aU[4][2], aV[4][2];
    #pragma unroll
    for (int r = 0; r < 4; r++) {
        aU[r][0] = aU[r][1] = 0ull;
        aV[r][0] = aV[r][1] = 0ull;
    }
    int la_m = tid >> 2;
    int la_k = (tid & 3) << 2;
    int lb_k = tid >> 4;
    int lb_n = (tid & 15) << 2;
    int am = m0 + la_m;

    float ra[4], r1[4], r2[4];
    #pragma unroll
    for (int q = 0; q < 4; q++) {
        int ak = la_k + q;
        ra[q] = (am < M && ak < K) ? A[(size_t)am * lda + ak] : 0.f;
        int bn = n0 + lb_n + q;
        float v1 = 0.f, v2 = 0.f;
        if (lb_k < K && bn < N) {
            size_t o = (size_t)lb_k * ldb + bn;
            v1 = B1[o]; v2 = B2[o];
        }
        r1[q] = sub ? (v1 - v2) : v1;
        r2[q] = v2;
    }
    #pragma unroll
    for (int q = 0; q < 4; q++) {
        As[0][(la_k + q) * 68 + la_m] = ra[q];
        B1s[0][lb_k * 68 + lb_n + q] = r1[q];
        B2s[0][lb_k * 68 + lb_n + q] = r2[q];
    }
    __syncthreads();

    int buf = 0;
    for (int k0 = 0; k0 < K; k0 += 16) {
        int nk = k0 + 16;
        if (nk < K) {
            #pragma unroll
            for (int q = 0; q < 4; q++) {
                int ak = nk + la_k + q;
                ra[q] = (am < M && ak < K) ? A[(size_t)am * lda + ak] : 0.f;
                int bn = n0 + lb_n + q;
                int bk = nk + lb_k;
                float v1 = 0.f, v2 = 0.f;
                if (bk < K && bn < N) {
                    size_t o = (size_t)bk * ldb + bn;
                    v1 = B1[o]; v2 = B2[o];
                }
                r1[q] = sub ? (v1 - v2) : v1;
                r2[q] = v2;
            }
        }
        const float* Ab  = As[buf];
        const float* B1b = B1s[buf];
        const float* B2b = B2s[buf];
        #pragma unroll
        for (int kk = 0; kk < 16; kk++) {
            float4 af = *(const float4*)&Ab[kk * 68 + (ty << 2)];
            ulonglong2 b1t = *(const ulonglong2*)&B1b[kk * 68 + (tx << 2)];
            ulonglong2 b2t = *(const ulonglong2*)&B2b[kk * 68 + (tx << 2)];
            float a[4] = {af.x, af.y, af.z, af.w};
            #pragma unroll
            for (int r = 0; r < 4; r++) {
                ull ap = pk2(a[r]);
                fma2(aU[r][0], ap, b1t.x);
                fma2(aU[r][1], ap, b1t.y);
                fma2(aV[r][0], ap, b2t.x);
                fma2(aV[r][1], ap, b2t.y);
            }
        }
        if (nk < K) {
            int nb = buf ^ 1;
            #pragma unroll
            for (int q = 0; q < 4; q++) {
                As[nb][(la_k + q) * 68 + la_m] = ra[q];
                B1s[nb][lb_k * 68 + lb_n + q] = r1[q];
                B2s[nb][lb_k * 68 + lb_n + q] = r2[q];
            }
            __syncthreads();
            buf = nb;
        }
    }

    #pragma unroll
    for (int r = 0; r < 4; r++) {
        int m = m0 + (ty << 2) + r;
        if (m >= M) continue;
        float u[4], v[4];
        unpk(aU[r][0], u[0], u[1]); unpk(aU[r][1], u[2], u[3]);
        unpk(aV[r][0], v[0], v[1]); unpk(aV[r][1], v[2], v[3]);
        #pragma unroll
        for (int c = 0; c < 4; c++) {
            int n = n0 + (tx << 2) + c;
            if (n >= N) continue;
            Uo[(size_t)m * ldu + n] = u[c];
            Vo[(size_t)m * ldu + n] = v[c];
        }
    }
}

// ---------------- global max pool, stage 1: partial max over 40 nodes ------------------
__global__ void gmax1_kernel() {
    int b = blockIdx.x, g = blockIdx.y, c = threadIdx.x;
    const float* p = g_sf + ((size_t)(b * NPTS) + g * 40) * 128 + c;
    float m = -3.3e38f;
    #pragma unroll 8
    for (int n = 0; n < 40; n++) m = fmaxf(m, p[n * 128]);
    g_pmax[(b * 25 + g) * 128 + c] = m;
}

// ---------------- stage 2: finish max + hg = g @ ec_w1[256:384] + ec_b1 ----------------
__global__ void hg2_kernel(const float* __restrict__ w1, const float* __restrict__ b1) {
    __shared__ float sg[128];
    int b = blockIdx.x, c = threadIdx.x;
    float m = -3.3e38f;
    #pragma unroll
    for (int g = 0; g < 25; g++) m = fmaxf(m, g_pmax[(b * 25 + g) * 128 + c]);
    sg[c] = m;
    __syncthreads();
    float s = b1[c];
    #pragma unroll 4
    for (int d = 0; d < 128; d++) s += sg[d] * w1[(256 + d) * 128 + c];
    g_hg[b * 128 + c] = s;
}

// ---------------- pair kernel: 64x64 tile, 4x4 pairs/thread ----------------
__global__ void __launch_bounds__(256)
pair_kernel(const float* __restrict__ w2, const float* __restrict__ b2,
            float* __restrict__ out) {
    int bx = blockIdx.x, by = blockIdx.y;
    if (bx < by) return;
    int b = blockIdx.z;
    extern __shared__ float ps[];
    float* s_hi = ps;
    float* s_hj = ps + 64 * 132;
    float* s_w  = ps + 2 * 64 * 132;

    int tid = threadIdx.y * 16 + threadIdx.x;
    int bi0 = by * 64, bj0 = bx * 64;

    for (int t = tid; t < 64 * 32; t += 256) {
        int r = t >> 5, c4 = (t & 31) << 2;
        int gi = bi0 + r;
        float4 v = make_float4(0.f, 0.f, 0.f, 0.f);
        if (gi < NPTS) v = *(const float4*)&g_hi[((size_t)(b * NPTS + gi)) * 128 + c4];
        *(float4*)&s_hi[r * 132 + c4] = v;
        int gj = bj0 + r;
        float4 u = make_float4(0.f, 0.f, 0.f, 0.f);
        if (gj < NPTS) {
            u = *(const float4*)&g_hjg[((size_t)(b * NPTS + gj)) * 128 + c4];
            float4 hgv = *(const float4*)&g_hg[b * 128 + c4];
            u.x += hgv.x; u.y += hgv.y; u.z += hgv.z; u.w += hgv.w;
        }
        *(float4*)&s_hj[r * 132 + c4] = u;
    }
    if (tid < 32) *(float4*)&s_w[tid * 4] = *(const float4*)&w2[tid * 4];
    __syncthreads();

    int ri0 = threadIdx.y * 4, cj0 = threadIdx.x * 4;
    float acc[4][4] = {};
    for (int c4 = 0; c4 < 128; c4 += 4) {
        float4 w = *(const float4*)&s_w[c4];
        float4 A[4], H[4];
        #pragma unroll
        for (int r = 0; r < 4; r++) A[r] = *(const float4*)&s_hi[(ri0 + r) * 132 + c4];
        #pragma unroll
        for (int c = 0; c < 4; c++) H[c] = *(const float4*)&s_hj[(cj0 + c) * 132 + c4];
        #pragma unroll
        for (int r = 0; r < 4; r++)
            #pragma unroll
            for (int c = 0; c < 4; c++) {
                acc[r][c] += fmaxf(A[r].x + H[c].x, 0.f) * w.x
                           + fmaxf(A[r].y + H[c].y, 0.f) * w.y
                           + fmaxf(A[r].z + H[c].z, 0.f) * w.z
                           + fmaxf(A[r].w + H[c].w, 0.f) * w.w;
            }
    }

    float bias2 = b2[0];
    #pragma unroll
    for (int r = 0; r < 4; r++) {
        int gi = bi0 + ri0 + r;
        #pragma unroll
        for (int c = 0; c < 4; c++) {
            int gj = bj0 + cj0 + c;
            if (gj < NPTS && gi < gj) {
                float m = acc[r][c] + bias2;
                int p = gi * (NPTS - 1) - (gi * (gi - 1)) / 2 + (gj - gi - 1);
                int off = b * NPAIR + p;
                out[off] = 1.f / (1.f + __expf(-m));
                out[BATCH * NPAIR + off] = m;
            }
        }
    }
}

// ============================ host side ============================
static void* sym_addr(const void* s) {
    void* p = nullptr;
    cudaGetSymbolAddress(&p, s);
    return p;
}

extern "C" void kernel_launch(void* const* d_in, const int* in_sizes, int n_in,
                              void* d_out, int out_size) {
    const float* in[21];
    for (int i = 0; i < 21; i++) in[i] = (const float*)d_in[i];
    const float* pos   = in[0];
    const float* c1_w1 = in[1];  const float* c1_b1 = in[2];
    const float* c1_w2 = in[3];  const float* c1_b2 = in[4];
    const float* c2_w1 = in[5];  const float* c2_b1 = in[6];
    const float* c2_w2 = in[7];  const float* c2_b2 = in[8];
    const float* c3_w1 = in[9];  const float* c3_b1 = in[10];
    const float* c3_w2 = in[11]; const float* c3_b2 = in[12];
    const float* sm_w1 = in[13]; const float* sm_b1 = in[14];
    const float* sm_w2 = in[15]; const float* sm_b2 = in[16];
    const float* ec_w1 = in[17]; const float* ec_b1 = in[18];
    const float* ec_w2 = in[19]; const float* ec_b2 = in[20];

    float* x1  = (float*)sym_addr(g_x1);
    float* x2  = (float*)sym_addr(g_x2);
    float* U   = (float*)sym_addr(g_U);
    float* V   = (float*)sym_addr(g_V);
    float* G   = (float*)sym_addr(g_G);
    float* cat = (float*)sym_addr(g_cat);
    float* smh = (float*)sym_addr(g_smh);
    float* sf  = (float*)sym_addr(g_sf);
    float* hi  = (float*)sym_addr(g_hi);
    float* hjg = (float*)sym_addr(g_hjg);

    cudaStream_t s1;
    cudaStreamCreateWithFlags(&s1, cudaStreamNonBlocking);
    cudaEvent_t ev[10];
    for (int i = 0; i < 10; i++) cudaEventCreateWithFlags(&ev[i], cudaEventDisableTiming);
    int ei = 0;

    struct LayerP {
        const float* x; int lda, C, H, H2;
        const float* w1; const float* b1; const float* w2; const float* b2;
        float* outp; int ldo; float* outc;
    } L[3] = {
        { pos, 3,   3,   16,  32,  c1_w1, c1_b1, c1_w2, c1_b2, cat + 0,   672, x1 },
        { x1,  32,  32,  64,  128, c2_w1, c2_b1, c2_w2, c2_b2, cat + 32,  672, x2 },
        { x2,  128, 128, 256, 512, c3_w1, c3_b1, c3_w2, c3_b2, cat + 160, 672, nullptr },
    };

    for (int l = 0; l < 3; l++) {
        cudaEventRecord(ev[ei], 0);
        cudaStreamWaitEvent(s1, ev[ei], 0); ei++;
        dim3 guv((BNODES + 63) / 64, (L[l].H + 63) / 64);
        gemm_uv_kernel<<<guv, 256, 0, s1>>>(L[l].x, L[l].lda, L[l].w1,
                                            L[l].w1 + (size_t)L[l].C * L[l].H, L[l].H,
                                            U, V, L[l].H, BNODES, L[l].H, L[l].C, 1);
        cudaEventRecord(ev[ei], s1);

        xxt_kernel<<<dim3(36, BATCH), 256>>>(L[l].x, L[l].lda, L[l].C, G);
        topk_kernel<<<BNODES / 8, 256>>>(G);

        cudaStreamWaitEvent(0, ev[ei], 0); ei++;
        fused_edge_mma<<<dim3(125, (L[l].H2 + 127) / 128), 256>>>(
            U, V, L[l].b1, L[l].w2, L[l].b2, L[l].outp, L[l].ldo, L[l].outc,
            L[l].H, L[l].H2);
    }

    // sm MLP via bf16-split mma: [2000,672] -> relu 256 -> 128
    {
        dim3 g1((BNODES + 63) / 64, 4);    // N=256 -> 4 tiles of 64
        gemm_mma64<<<g1, 256>>>(cat, 672, sm_w1, 256, smh, 256, BNODES, 256, 672, sm_b1, 1);
        dim3 g2((BNODES + 63) / 64, 2);    // N=128 -> 2 tiles of 64
        gemm_mma64<<<g2, 256>>>(smh, 256, sm_w2, 128, sf, 128, BNODES, 128, 256, sm_b2, 0);
    }

    // fork: hi/hjg dual GEMM on s1, gmax(2-stage)+hg on main
    cudaEventRecord(ev[ei], 0);
    cudaStreamWaitEvent(s1, ev[ei], 0); ei++;
    dim3 ghh((BNODES + 63) / 64, 2);
    gemm_uv_kernel<<<ghh, 256, 0, s1>>>(sf, 128, ec_w1 + 128 * 128, ec_w1, 128,
                                        hjg, hi, 128, BNODES, 128, 128, 0);
    cudaEventRecord(ev[ei], s1);

    gmax1_kernel<<<dim3(BATCH, 25), 128>>>();
    hg2_kernel<<<BATCH, 128>>>(ec_w1, ec_b1);

    cudaStreamWaitEvent(0, ev[ei], 0); ei++;

    // fused pair stage -> d_out = [pair_prob (B*P), mlp_out (B*P)]
    size_t psmem = (2 * 64 * 132 + 128) * sizeof(float);
    cudaFuncSetAttribute(pair_kernel, cudaFuncAttributeMaxDynamicSharedMemorySize, (int)psmem);
    pair_kernel<<<dim3(16, 16, BATCH), dim3(16, 16), psmem>>>(ec_w2, ec_b2, (float*)d_out);
}